// round 10
// baseline (speedup 1.0000x reference)
#include <cuda_runtime.h>
#include <cstdint>
#include <math.h>

#define NPIX 9409
#define LDF  9412          /* padded row stride for E/g; pads stay 0 forever */
#define CIN  512
#define CMIX 1024
#define C1N  256
#define C2N  512
#define BN_INV 0.9999950000374997f

// ------------------------- scratch (static device) --------------------------
__device__ float d_xmixT[NPIX * CMIX];        // [9409, 1024] (tf32-rounded)
__device__ float d_tT  [NPIX * C1N];          // [9409, 256]  (tf32-rounded)
__device__ float d_g   [C2N * LDF];           // [512, 9412]  (tf32-rounded)
__device__ float d_f   [NPIX * LDF];          // [9409, 9412] E = exp(f/16 - mhat[n])
__device__ float d_yT  [NPIX * C2N];          // [9409, 512]
__device__ float d_ds  [NPIX];                // |t_n|^2 / 16
__device__ float d_mhat[NPIX];                // sqrt(ds[n]*dsmax)
__device__ float d_denom[NPIX];               // sum_m E[n,m]
__device__ float d_dsmax;
__device__ float d_wtR [C1N * CMIX];          // rounded weights
__device__ float d_wgR [C2N * CMIX];
__device__ float d_woR [CIN * C2N];

// ------------------------- helpers ------------------------------------------
__device__ __forceinline__ uint32_t f2tf(float v) {
    uint32_t u;
    asm("cvt.rna.tf32.f32 %0, %1;" : "=r"(u) : "f"(v));
    return u;
}
__device__ __forceinline__ float rtf(float v) { return __uint_as_float(f2tf(v)); }

__device__ __forceinline__ void mma_tf32(float c[4], uint32_t a0, uint32_t a1,
                                         uint32_t a2, uint32_t a3,
                                         uint32_t b0, uint32_t b1) {
    asm volatile(
        "mma.sync.aligned.m16n8k8.row.col.f32.tf32.tf32.f32 "
        "{%0,%1,%2,%3}, {%4,%5,%6,%7}, {%8,%9}, {%0,%1,%2,%3};"
        : "+f"(c[0]), "+f"(c[1]), "+f"(c[2]), "+f"(c[3])
        : "r"(a0), "r"(a1), "r"(a2), "r"(a3), "r"(b0), "r"(b1));
}

// fast exp on the FMA pipe (no MUFU); clamp guarantees nonzero result
__device__ __forceinline__ float fexp(float x) {
    x = fmaxf(x, -87.0f);
    float t = x * 1.4426950408889634f;
    float fl = floorf(t);
    float f = t - fl;
    float p = 1.52527338e-5f;
    p = fmaf(p, f, 1.54035304e-4f);
    p = fmaf(p, f, 1.33335581e-3f);
    p = fmaf(p, f, 9.61812911e-3f);
    p = fmaf(p, f, 5.55041087e-2f);
    p = fmaf(p, f, 2.40226507e-1f);
    p = fmaf(p, f, 6.93147181e-1f);
    p = fmaf(p, f, 1.0f);
    int i = (int)fl;
    return p * __int_as_float((i + 127) << 23);
}

// ------------------------- small prep kernels -------------------------------
__global__ void zero_k() {
    int i = blockIdx.x * 256 + threadIdx.x;
    if (i < NPIX) d_denom[i] = 0.f;
    if (i == 0) d_dsmax = 0.f;
}

__global__ void round_k(const float* __restrict__ in, float* __restrict__ out, int n) {
    int i = blockIdx.x * 256 + threadIdx.x;
    if (i < n) out[i] = rtf(in[i]);
}

// xmixT[n, k] = tf32round( (k<512) ? x[k, n] : pos[k-512, n] )
__global__ void concatT_k(const float* __restrict__ x, const float* __restrict__ pos) {
    __shared__ float tile[32][33];
    const float* S = blockIdx.z ? pos : x;
    int c0 = blockIdx.y * 32, n0 = blockIdx.x * 32;
    int tx = threadIdx.x, ty = threadIdx.y;
    #pragma unroll
    for (int i = 0; i < 32; i += 8) {
        int c = c0 + ty + i, n = n0 + tx;
        if (n < NPIX) tile[ty + i][tx] = S[(size_t)c * NPIX + n];
    }
    __syncthreads();
    int kbase = blockIdx.z * 512 + c0;
    #pragma unroll
    for (int i = 0; i < 32; i += 8) {
        int n = n0 + ty + i;
        if (n < NPIX) d_xmixT[(size_t)n * CMIX + kbase + tx] = rtf(tile[tx][ty + i]);
    }
}

// ds[n] = |t_n|^2/16; dsmax = max_n ds[n] (atomicMax on nonneg floats as ints)
__global__ void __launch_bounds__(256) ds_k() {
    int row = blockIdx.x * 8 + (threadIdx.x >> 5);
    if (row >= NPIX) return;
    int lane = threadIdx.x & 31;
    const float* p = d_tT + (size_t)row * C1N;
    float s = 0.f;
    #pragma unroll
    for (int i = 0; i < 2; ++i) {
        float4 v = *(const float4*)(p + lane * 8 + i * 4);
        s += v.x * v.x + v.y * v.y + v.z * v.z + v.w * v.w;
    }
    #pragma unroll
    for (int off = 16; off > 0; off >>= 1) s += __shfl_xor_sync(0xFFFFFFFFu, s, off);
    if (lane == 0) {
        float dsv = s * 0.0625f;
        d_ds[row] = dsv;
        atomicMax((int*)&d_dsmax, __float_as_int(dsv));
    }
}

__global__ void mhat_k() {
    int i = blockIdx.x * 256 + threadIdx.x;
    if (i < NPIX) d_mhat[i] = sqrtf(d_ds[i] * d_dsmax);
}

// yT[n,c] := tf32round(yT[n,c] / denom[n])
__global__ void __launch_bounds__(256) scale_yT_k() {
    int idx = blockIdx.x * 256 + threadIdx.x;     // float4 groups
    if (idx >= NPIX * 128) return;
    int n = idx >> 7;
    float r = 1.f / d_denom[n];
    float4* p = (float4*)d_yT + idx;
    float4 v = *p;
    v.x = rtf(v.x * r); v.y = rtf(v.y * r); v.z = rtf(v.z * r); v.w = rtf(v.w * r);
    *p = v;
}

// ------------------------- mma.sync tf32 GEMM (256 thr), cp.async -----------
// D[M,N] = epi( sum_k A[m,k]*B[n,k] );  A [M,K] lda, B [N,K] ldb, C [M,N] ldc
// EPI 0: *alpha   1: +p1[gm]   2: relu((acc+p1[gn])*p2[gn]*BN_INV+p3[gn])
// EXPOUT: symmetric Gram tile kernel; writes E=exp(v*?-mhat[row]) for both
//         orientations (only bx>=by tiles launched; alpha pre-applied to v)
#define GEMM_SMEM 73728   /* 2 x (A 18432 + B 18432); >= 66048 staging */

template <int EPI, int ROUND, int EXPOUT>
__global__ void __launch_bounds__(256, 2)
gemm_mma(const float* __restrict__ A, const float* __restrict__ B, float* __restrict__ C,
         int M, int Nn, int K, int lda, int ldb, int ldc,
         const float* __restrict__ p1, const float* __restrict__ p2,
         const float* __restrict__ p3, float alpha,
         const float* __restrict__ mhat) {
    if (EXPOUT && blockIdx.y > blockIdx.x) return;
    extern __shared__ char dsm[];
    float* smf = (float*)dsm;
    const uint32_t sbase = (uint32_t)__cvta_generic_to_shared(dsm);

    const int tid  = threadIdx.x;
    const int lane = tid & 31, wid = tid >> 5;
    const int wm = wid & 1;          // 2 warp rows (64 m each)
    const int wn = wid >> 1;         // 4 warp cols (32 n each)
    const int g   = lane >> 2;       // 0..7
    const int tig = lane & 3;        // 0..3
    const int m0 = blockIdx.y * 128, n0 = blockIdx.x * 128;

    const int lr  = tid >> 3;        // 0..31
    const int kv4 = (tid & 7) << 2;  // 0,4,...,28

    float acc[4][4][4];
    #pragma unroll
    for (int mt = 0; mt < 4; ++mt)
        #pragma unroll
        for (int nt = 0; nt < 4; ++nt)
            #pragma unroll
            for (int c = 0; c < 4; ++c) acc[mt][nt][c] = 0.f;

    const int KT = (K + 31) >> 5;

    auto issue = [&](int t) {
        const int gk = (t << 5) + kv4;
        uint32_t sa = sbase + (uint32_t)(t & 1) * 36864u;
        uint32_t sb = sa + 18432u;
        #pragma unroll
        for (int i = 0; i < 4; ++i) {
            int row = lr + (i << 5);
            uint32_t off = (uint32_t)(row * 144 + (kv4 << 2));
            const float* pa = A + (size_t)(m0 + row) * lda + gk;
            int sza = ((m0 + row) < M && gk < K) ? 16 : 0;
            if (!sza) pa = A;
            asm volatile("cp.async.cg.shared.global [%0], [%1], 16, %2;"
                         :: "r"(sa + off), "l"(pa), "r"(sza) : "memory");
            const float* pb = B + (size_t)(n0 + row) * ldb + gk;
            int szb = ((n0 + row) < Nn && gk < K) ? 16 : 0;
            if (!szb) pb = B;
            asm volatile("cp.async.cg.shared.global [%0], [%1], 16, %2;"
                         :: "r"(sb + off), "l"(pb), "r"(szb) : "memory");
        }
        asm volatile("cp.async.commit_group;" ::: "memory");
    };

    issue(0);
    for (int t = 0; t < KT; ++t) {
        if (t + 1 < KT) {
            issue(t + 1);
            asm volatile("cp.async.wait_group 1;" ::: "memory");
        } else {
            asm volatile("cp.async.wait_group 0;" ::: "memory");
        }
        __syncthreads();

        const float* As = smf + (t & 1) * 9216;
        const float* Bs = As + 4608;

        #pragma unroll
        for (int ks = 0; ks < 4; ++ks) {
            const int kk = ks * 8;
            uint32_t bf[4][2];
            #pragma unroll
            for (int nt = 0; nt < 4; ++nt) {
                int col = wn * 32 + nt * 8 + g;
                bf[nt][0] = __float_as_uint(Bs[col * 36 + kk + tig]);
                bf[nt][1] = __float_as_uint(Bs[col * 36 + kk + tig + 4]);
            }
            #pragma unroll
            for (int mt = 0; mt < 4; ++mt) {
                int row = wm * 64 + mt * 16;
                uint32_t a0 = __float_as_uint(As[(row + g    ) * 36 + kk + tig]);
                uint32_t a1 = __float_as_uint(As[(row + g + 8) * 36 + kk + tig]);
                uint32_t a2 = __float_as_uint(As[(row + g    ) * 36 + kk + tig + 4]);
                uint32_t a3 = __float_as_uint(As[(row + g + 8) * 36 + kk + tig + 4]);
                #pragma unroll
                for (int nt = 0; nt < 4; ++nt)
                    mma_tf32(acc[mt][nt], a0, a1, a2, a3, bf[nt][0], bf[nt][1]);
            }
        }
        __syncthreads();
    }

    // ------------------------- epilogue -------------------------
    if (!EXPOUT) {
        #pragma unroll
        for (int mt = 0; mt < 4; ++mt) {
            #pragma unroll
            for (int half = 0; half < 2; ++half) {
                int gm = m0 + wm * 64 + mt * 16 + g + half * 8;
                if (gm >= M) continue;
                float rp = (EPI == 1) ? p1[gm] : 0.f;
                float* crow = C + (size_t)gm * ldc;
                #pragma unroll
                for (int nt = 0; nt < 4; ++nt) {
                    #pragma unroll
                    for (int cc = 0; cc < 2; ++cc) {
                        int gn = n0 + wn * 32 + nt * 8 + tig * 2 + cc;
                        if (gn < Nn) {
                            float v = acc[mt][nt][half * 2 + cc];
                            if (EPI == 0)      v *= alpha;
                            else if (EPI == 1) v += rp;
                            else               v = fmaxf(fmaf(v + p1[gn], p2[gn] * BN_INV, p3[gn]), 0.f);
                            if (ROUND) v = rtf(v);
                            crow[gn] = v;
                        }
                    }
                }
            }
        }
    } else {
        // stage raw scaled scores, then write exp for both orientations
        float* stg = smf;   // 128x129 staging (66 KB); mainloop buffers dead
        #pragma unroll
        for (int mt = 0; mt < 4; ++mt)
            #pragma unroll
            for (int half = 0; half < 2; ++half) {
                int lm = wm * 64 + mt * 16 + g + half * 8;
                #pragma unroll
                for (int nt = 0; nt < 4; ++nt)
                    #pragma unroll
                    for (int cc = 0; cc < 2; ++cc) {
                        int ln = wn * 32 + nt * 8 + tig * 2 + cc;
                        stg[lm * 129 + ln] = acc[mt][nt][half * 2 + cc] * alpha;
                    }
            }
        __syncthreads();
        const int cL = tid & 127, rO = tid >> 7;
        #pragma unroll 4
        for (int j = 0; j < 64; ++j) {
            int r = (j << 1) + rO;
            int gm = m0 + r, gn = n0 + cL;
            if (gm < M && gn < Nn)
                C[(size_t)gm * ldc + gn] = rtf(fexp(stg[r * 129 + cL] - mhat[gm]));
        }
        if (blockIdx.x != blockIdx.y) {
            #pragma unroll 4
            for (int j = 0; j < 64; ++j) {
                int r = (j << 1) + rO;
                int gn = n0 + r, gm = m0 + cL;
                if (gn < Nn && gm < M)
                    C[(size_t)gn * ldc + gm] = rtf(fexp(stg[cL * 129 + r] - mhat[gn]));
            }
        }
    }
}

// ------------------------- y-GEMM: 128x256 tile, 256 thr, warp 64x64 --------
// yT[n,c] = sum_m E[n,m] g[c,m]; each CTA also sums 64 of its E rows -> denom
// 3-stage cp.async pipeline, single __syncthreads per k-tile
#define Y_SMEM 165888   /* 3 stages x (A 18432 + B 36864) */

__global__ void __launch_bounds__(256, 1)
gemm_y(const float* __restrict__ A, const float* __restrict__ B,
       float* __restrict__ C, float* __restrict__ denom) {
    extern __shared__ char dsm[];
    float* smf = (float*)dsm;
    const uint32_t sbase = (uint32_t)__cvta_generic_to_shared(dsm);

    const int tid  = threadIdx.x;
    const int lane = tid & 31, wid = tid >> 5;
    const int wm = wid & 1;          // 2 warp rows (64 m each)
    const int wn = wid >> 1;         // 4 warp cols (64 n each)
    const int g   = lane >> 2;
    const int tig = lane & 3;
    const int m0 = blockIdx.y * 128, n0 = blockIdx.x * 256;
    const int M = NPIX, K = LDF;

    float acc[4][8][4];
    #pragma unroll
    for (int mt = 0; mt < 4; ++mt)
        #pragma unroll
        for (int nt = 0; nt < 8; ++nt)
            #pragma unroll
            for (int c = 0; c < 4; ++c) acc[mt][nt][c] = 0.f;
    float dpart = 0.f;
    // denom rows: this CTA sums A rows [bx*64, bx*64+64); 4 threads per row
    const int drow = (blockIdx.x << 6) + (tid >> 2);   // local row in A tile
    const int dq   = (tid & 3) * 8;                    // 8 floats per thread

    auto issue = [&](int t) {
        const int stage = t % 3;
        uint32_t sa = sbase + (uint32_t)stage * 55296u;
        uint32_t sb = sa + 18432u;
        const int kbase = t << 5;
        #pragma unroll
        for (int i = 0; i < 4; ++i) {        // A: 128 rows x 8 chunks
            int id = tid + (i << 8);
            int row = id >> 3, ch = id & 7;
            int gk = kbase + (ch << 2);
            uint32_t off = (uint32_t)(row * 144 + (ch << 4));
            const float* pa = A + (size_t)(m0 + row) * K + gk;
            int sza = ((m0 + row) < M && gk < K) ? 16 : 0;
            if (!sza) pa = A;
            asm volatile("cp.async.cg.shared.global [%0], [%1], 16, %2;"
                         :: "r"(sa + off), "l"(pa), "r"(sza) : "memory");
        }
        #pragma unroll
        for (int i = 0; i < 8; ++i) {        // B: 256 rows x 8 chunks
            int id = tid + (i << 8);
            int row = id >> 3, ch = id & 7;
            int gk = kbase + (ch << 2);
            uint32_t off = (uint32_t)(row * 144 + (ch << 4));
            const float* pb = B + (size_t)(n0 + row) * K + gk;
            int szb = (gk < K) ? 16 : 0;
            if (!szb) pb = B;
            asm volatile("cp.async.cg.shared.global [%0], [%1], 16, %2;"
                         :: "r"(sb + off), "l"(pb), "r"(szb) : "memory");
        }
        asm volatile("cp.async.commit_group;" ::: "memory");
    };

    const int KT = (K + 31) >> 5;   // 295
    issue(0);
    if (KT > 1) issue(1);
    for (int t = 0; t < KT; ++t) {
        if (t + 1 < KT) asm volatile("cp.async.wait_group 1;" ::: "memory");
        else            asm volatile("cp.async.wait_group 0;" ::: "memory");
        __syncthreads();
        if (t + 2 < KT) issue(t + 2);

        const float* As = smf + (t % 3) * 13824;
        const float* Bs = As + 4608;

        // denom partial: 8 floats of one A row
        {
            float4 v0 = *(const float4*)&As[drow * 36 + dq];
            float4 v1 = *(const float4*)&As[drow * 36 + dq + 4];
            dpart += (v0.x + v0.y) + (v0.z + v0.w) + (v1.x + v1.y) + (v1.z + v1.w);
        }

        #pragma unroll
        for (int ks = 0; ks < 4; ++ks) {
            const int kk = ks * 8;
            uint32_t bf[8][2];
            #pragma unroll
            for (int nt = 0; nt < 8; ++nt) {
                int col = wn * 64 + nt * 8 + g;
                bf[nt][0] = __float_as_uint(Bs[col * 36 + kk + tig]);
                bf[nt][1] = __float_as_uint(Bs[col * 36 + kk + tig + 4]);
            }
            #pragma unroll
            for (int mt = 0; mt < 4; ++mt) {
                int row = wm * 64 + mt * 16;
                uint32_t a0 = __float_as_uint(As[(row + g    ) * 36 + kk + tig]);
                uint32_t a1 = __float_as_uint(As[(row + g + 8) * 36 + kk + tig]);
                uint32_t a2 = __float_as_uint(As[(row + g    ) * 36 + kk + tig + 4]);
                uint32_t a3 = __float_as_uint(As[(row + g + 8) * 36 + kk + tig + 4]);
                #pragma unroll
                for (int nt = 0; nt < 8; ++nt)
                    mma_tf32(acc[mt][nt], a0, a1, a2, a3, bf[nt][0], bf[nt][1]);
            }
        }
    }

    // denom reduce: 4 consecutive lanes share a row
    dpart += __shfl_xor_sync(0xFFFFFFFFu, dpart, 1);
    dpart += __shfl_xor_sync(0xFFFFFFFFu, dpart, 2);
    if ((tid & 3) == 0) {
        int gm = m0 + drow;
        if (gm < M) atomicAdd(&denom[gm], dpart);
    }

    #pragma unroll
    for (int mt = 0; mt < 4; ++mt) {
        #pragma unroll
        for (int half = 0; half < 2; ++half) {
            int gm = m0 + wm * 64 + mt * 16 + g + half * 8;
            if (gm >= M) continue;
            float* crow = C + (size_t)gm * C2N;
            #pragma unroll
            for (int nt = 0; nt < 8; ++nt) {
                #pragma unroll
                for (int cc = 0; cc < 2; ++cc) {
                    int gn = n0 + wn * 64 + nt * 8 + tig * 2 + cc;
                    crow[gn] = acc[mt][nt][half * 2 + cc];
                }
            }
        }
    }
}

// ---------------------------------------------------------------------------
extern "C" void kernel_launch(void* const* d_in, const int* in_sizes, int n_in,
                              void* d_out, int out_size) {
    const float* x       = (const float*)d_in[0];
    const float* pos     = (const float*)d_in[1];
    const float* w_theta = (const float*)d_in[2];
    const float* b_theta = (const float*)d_in[3];
    const float* gamma_t = (const float*)d_in[4];
    const float* beta_t  = (const float*)d_in[5];
    const float* w_g     = (const float*)d_in[6];
    const float* b_g     = (const float*)d_in[7];
    const float* w_out   = (const float*)d_in[8];
    const float* b_out   = (const float*)d_in[9];
    float* out = (float*)d_out;

    cudaFuncSetAttribute(gemm_mma<2,1,0>, cudaFuncAttributeMaxDynamicSharedMemorySize, GEMM_SMEM);
    cudaFuncSetAttribute(gemm_mma<1,1,0>, cudaFuncAttributeMaxDynamicSharedMemorySize, GEMM_SMEM);
    cudaFuncSetAttribute(gemm_mma<0,0,1>, cudaFuncAttributeMaxDynamicSharedMemorySize, GEMM_SMEM);
    cudaFuncSetAttribute(gemm_mma<1,0,0>, cudaFuncAttributeMaxDynamicSharedMemorySize, GEMM_SMEM);
    cudaFuncSetAttribute(gemm_y,          cudaFuncAttributeMaxDynamicSharedMemorySize, Y_SMEM);

    float *p_xmixT, *p_tT, *p_g, *p_f, *p_yT, *p_mhat, *p_denom, *p_wtR, *p_wgR, *p_woR;
    cudaGetSymbolAddress((void**)&p_xmixT, d_xmixT);
    cudaGetSymbolAddress((void**)&p_tT,    d_tT);
    cudaGetSymbolAddress((void**)&p_g,     d_g);
    cudaGetSymbolAddress((void**)&p_f,     d_f);
    cudaGetSymbolAddress((void**)&p_yT,    d_yT);
    cudaGetSymbolAddress((void**)&p_mhat,  d_mhat);
    cudaGetSymbolAddress((void**)&p_denom, d_denom);
    cudaGetSymbolAddress((void**)&p_wtR,   d_wtR);
    cudaGetSymbolAddress((void**)&p_wgR,   d_wgR);
    cudaGetSymbolAddress((void**)&p_woR,   d_woR);

    const int TM = 74;  // ceil(9409/128)

    // 0) reset accumulators (graph-replay safe) + round weights to tf32
    zero_k<<<37, 256>>>();
    round_k<<<(C1N * CMIX + 255) / 256, 256>>>(w_theta, p_wtR, C1N * CMIX);
    round_k<<<(C2N * CMIX + 255) / 256, 256>>>(w_g,     p_wgR, C2N * CMIX);
    round_k<<<(CIN * C2N  + 255) / 256, 256>>>(w_out,   p_woR, CIN * C2N);

    // 1) xmixT = round(concat(x,pos)^T)   [9409, 1024]
    concatT_k<<<dim3(295, 16, 2), dim3(32, 8)>>>(x, pos);

    // 2) tT = round(relu(bn(xmixT @ w_theta^T)))   [9409, 256]
    gemm_mma<2,1,0><<<dim3(2, TM), 256, GEMM_SMEM>>>(
        p_xmixT, p_wtR, p_tT, NPIX, C1N, CMIX, CMIX, CMIX, C1N,
        b_theta, gamma_t, beta_t, 1.f, nullptr);

    // 3) ds[n] = |t_n|^2/16, dsmax; mhat[n] = sqrt(ds[n]*dsmax)  (>= row max)
    ds_k<<<(NPIX + 7) / 8, 256>>>();
    mhat_k<<<37, 256>>>();

    // 4) g = round(w_g @ xmixT^T + b_g)   [512, LDF]
    gemm_mma<1,1,0><<<dim3(TM, 4), 256, GEMM_SMEM>>>(
        p_wgR, p_xmixT, p_g, C2N, NPIX, CMIX, CMIX, CMIX, LDF,
        b_g, nullptr, nullptr, 1.f, nullptr);

    // 5) E = exp(tT@tT^T/16 - mhat[row])  — symmetric tiles + mirror, exp fused
    gemm_mma<0,0,1><<<dim3(TM, TM), 256, GEMM_SMEM>>>(
        p_tT, p_tT, p_f, NPIX, NPIX, C1N, C1N, C1N, LDF,
        nullptr, nullptr, nullptr, 0.0625f, p_mhat);

    // 6) yT[n,c] = sum_m E[n,m] g[c,m]; CTAs also accumulate denom[n]
    gemm_y<<<dim3(2, TM), 256, Y_SMEM>>>(p_f, p_g, p_yT, p_denom);

    // 7) yT *= 1/denom  (tf32-rounded)
    scale_yT_k<<<(NPIX * 128 + 255) / 256, 256>>>();

    // 8) out = w_out @ yT^T + b_out       [512, 9409]
    gemm_mma<1,0,0><<<dim3(TM, 4), 256, GEMM_SMEM>>>(
        p_woR, p_yT, out, CIN, NPIX, C2N, C2N, C2N, NPIX,
        b_out, nullptr, nullptr, 1.f, nullptr);
}

// round 11
// speedup vs baseline: 1.0025x; 1.0025x over previous
#include <cuda_runtime.h>
#include <cstdint>
#include <math.h>

#define NPIX 9409
#define LDF  9412          /* padded row stride for E/g; pads stay 0 forever */
#define CIN  512
#define CMIX 1024
#define C1N  256
#define C2N  512
#define BN_INV 0.9999950000374997f

// ------------------------- scratch (static device) --------------------------
__device__ float d_xmixT[NPIX * CMIX];        // [9409, 1024] (tf32-rounded)
__device__ float d_tT  [NPIX * C1N];          // [9409, 256]  (tf32-rounded)
__device__ float d_g   [C2N * LDF];           // [512, 9412]  (tf32-rounded)
__device__ float d_f   [NPIX * LDF];          // [9409, 9412] E = exp(f/16 - mhat[n])
__device__ float d_yT  [NPIX * C2N];          // [9409, 512]
__device__ float d_ds  [NPIX];                // |t_n|^2 / 16
__device__ float d_mhat[NPIX];                // sqrt(ds[n]*dsmax)
__device__ float d_denom[NPIX];               // sum_m E[n,m]
__device__ float d_dsmax;
__device__ float d_wtR [C1N * CMIX];          // rounded weights
__device__ float d_wgR [C2N * CMIX];
__device__ float d_woR [CIN * C2N];

// ------------------------- helpers ------------------------------------------
__device__ __forceinline__ uint32_t f2tf(float v) {
    uint32_t u;
    asm("cvt.rna.tf32.f32 %0, %1;" : "=r"(u) : "f"(v));
    return u;
}
__device__ __forceinline__ float rtf(float v) { return __uint_as_float(f2tf(v)); }

__device__ __forceinline__ void mma_tf32(float c[4], uint32_t a0, uint32_t a1,
                                         uint32_t a2, uint32_t a3,
                                         uint32_t b0, uint32_t b1) {
    asm volatile(
        "mma.sync.aligned.m16n8k8.row.col.f32.tf32.tf32.f32 "
        "{%0,%1,%2,%3}, {%4,%5,%6,%7}, {%8,%9}, {%0,%1,%2,%3};"
        : "+f"(c[0]), "+f"(c[1]), "+f"(c[2]), "+f"(c[3])
        : "r"(a0), "r"(a1), "r"(a2), "r"(a3), "r"(b0), "r"(b1));
}

// fast exp on the FMA pipe (no MUFU); clamp guarantees nonzero result
__device__ __forceinline__ float fexp(float x) {
    x = fmaxf(x, -87.0f);
    float t = x * 1.4426950408889634f;
    float fl = floorf(t);
    float f = t - fl;
    float p = 1.52527338e-5f;
    p = fmaf(p, f, 1.54035304e-4f);
    p = fmaf(p, f, 1.33335581e-3f);
    p = fmaf(p, f, 9.61812911e-3f);
    p = fmaf(p, f, 5.55041087e-2f);
    p = fmaf(p, f, 2.40226507e-1f);
    p = fmaf(p, f, 6.93147181e-1f);
    p = fmaf(p, f, 1.0f);
    int i = (int)fl;
    return p * __int_as_float((i + 127) << 23);
}

// ------------------------- small prep kernels -------------------------------
__global__ void zero_k() {
    int i = blockIdx.x * 256 + threadIdx.x;
    if (i < NPIX) d_denom[i] = 0.f;
    if (i == 0) d_dsmax = 0.f;
}

__global__ void round_k(const float* __restrict__ in, float* __restrict__ out, int n) {
    int i = blockIdx.x * 256 + threadIdx.x;
    if (i < n) out[i] = rtf(in[i]);
}

// xmixT[n, k] = tf32round( (k<512) ? x[k, n] : pos[k-512, n] )
__global__ void concatT_k(const float* __restrict__ x, const float* __restrict__ pos) {
    __shared__ float tile[32][33];
    const float* S = blockIdx.z ? pos : x;
    int c0 = blockIdx.y * 32, n0 = blockIdx.x * 32;
    int tx = threadIdx.x, ty = threadIdx.y;
    #pragma unroll
    for (int i = 0; i < 32; i += 8) {
        int c = c0 + ty + i, n = n0 + tx;
        if (n < NPIX) tile[ty + i][tx] = S[(size_t)c * NPIX + n];
    }
    __syncthreads();
    int kbase = blockIdx.z * 512 + c0;
    #pragma unroll
    for (int i = 0; i < 32; i += 8) {
        int n = n0 + ty + i;
        if (n < NPIX) d_xmixT[(size_t)n * CMIX + kbase + tx] = rtf(tile[tx][ty + i]);
    }
}

// ds[n] = |t_n|^2/16; dsmax = max_n ds[n] (atomicMax on nonneg floats as ints)
__global__ void __launch_bounds__(256) ds_k() {
    int row = blockIdx.x * 8 + (threadIdx.x >> 5);
    if (row >= NPIX) return;
    int lane = threadIdx.x & 31;
    const float* p = d_tT + (size_t)row * C1N;
    float s = 0.f;
    #pragma unroll
    for (int i = 0; i < 2; ++i) {
        float4 v = *(const float4*)(p + lane * 8 + i * 4);
        s += v.x * v.x + v.y * v.y + v.z * v.z + v.w * v.w;
    }
    #pragma unroll
    for (int off = 16; off > 0; off >>= 1) s += __shfl_xor_sync(0xFFFFFFFFu, s, off);
    if (lane == 0) {
        float dsv = s * 0.0625f;
        d_ds[row] = dsv;
        atomicMax((int*)&d_dsmax, __float_as_int(dsv));
    }
}

__global__ void mhat_k() {
    int i = blockIdx.x * 256 + threadIdx.x;
    if (i < NPIX) d_mhat[i] = sqrtf(d_ds[i] * d_dsmax);
}

// yT[n,c] := tf32round(yT[n,c] / denom[n])
__global__ void __launch_bounds__(256) scale_yT_k() {
    int idx = blockIdx.x * 256 + threadIdx.x;     // float4 groups
    if (idx >= NPIX * 128) return;
    int n = idx >> 7;
    float r = 1.f / d_denom[n];
    float4* p = (float4*)d_yT + idx;
    float4 v = *p;
    v.x = rtf(v.x * r); v.y = rtf(v.y * r); v.z = rtf(v.z * r); v.w = rtf(v.w * r);
    *p = v;
}

// ------------------------- mma.sync tf32 GEMM (256 thr), cp.async -----------
// D[M,N] = epi( sum_k A[m,k]*B[n,k] );  A [M,K] lda, B [N,K] ldb, C [M,N] ldc
// EPI 0: *alpha   1: +p1[gm]   2: relu((acc+p1[gn])*p2[gn]*BN_INV+p3[gn])
// EXPOUT: symmetric Gram tile kernel; writes E=exp(v*?-mhat[row]) for both
//         orientations (only bx>=by tiles launched; alpha pre-applied to v)
#define GEMM_SMEM 73728   /* 2 x (A 18432 + B 18432); >= 66048 staging */

template <int EPI, int ROUND, int EXPOUT>
__global__ void __launch_bounds__(256, 2)
gemm_mma(const float* __restrict__ A, const float* __restrict__ B, float* __restrict__ C,
         int M, int Nn, int K, int lda, int ldb, int ldc,
         const float* __restrict__ p1, const float* __restrict__ p2,
         const float* __restrict__ p3, float alpha,
         const float* __restrict__ mhat) {
    if (EXPOUT && blockIdx.y > blockIdx.x) return;
    extern __shared__ char dsm[];
    float* smf = (float*)dsm;
    const uint32_t sbase = (uint32_t)__cvta_generic_to_shared(dsm);

    const int tid  = threadIdx.x;
    const int lane = tid & 31, wid = tid >> 5;
    const int wm = wid & 1;          // 2 warp rows (64 m each)
    const int wn = wid >> 1;         // 4 warp cols (32 n each)
    const int g   = lane >> 2;       // 0..7
    const int tig = lane & 3;        // 0..3
    const int m0 = blockIdx.y * 128, n0 = blockIdx.x * 128;

    const int lr  = tid >> 3;        // 0..31
    const int kv4 = (tid & 7) << 2;  // 0,4,...,28

    float acc[4][4][4];
    #pragma unroll
    for (int mt = 0; mt < 4; ++mt)
        #pragma unroll
        for (int nt = 0; nt < 4; ++nt)
            #pragma unroll
            for (int c = 0; c < 4; ++c) acc[mt][nt][c] = 0.f;

    const int KT = (K + 31) >> 5;

    auto issue = [&](int t) {
        const int gk = (t << 5) + kv4;
        uint32_t sa = sbase + (uint32_t)(t & 1) * 36864u;
        uint32_t sb = sa + 18432u;
        #pragma unroll
        for (int i = 0; i < 4; ++i) {
            int row = lr + (i << 5);
            uint32_t off = (uint32_t)(row * 144 + (kv4 << 2));
            const float* pa = A + (size_t)(m0 + row) * lda + gk;
            int sza = ((m0 + row) < M && gk < K) ? 16 : 0;
            if (!sza) pa = A;
            asm volatile("cp.async.cg.shared.global [%0], [%1], 16, %2;"
                         :: "r"(sa + off), "l"(pa), "r"(sza) : "memory");
            const float* pb = B + (size_t)(n0 + row) * ldb + gk;
            int szb = ((n0 + row) < Nn && gk < K) ? 16 : 0;
            if (!szb) pb = B;
            asm volatile("cp.async.cg.shared.global [%0], [%1], 16, %2;"
                         :: "r"(sb + off), "l"(pb), "r"(szb) : "memory");
        }
        asm volatile("cp.async.commit_group;" ::: "memory");
    };

    issue(0);
    for (int t = 0; t < KT; ++t) {
        if (t + 1 < KT) {
            issue(t + 1);
            asm volatile("cp.async.wait_group 1;" ::: "memory");
        } else {
            asm volatile("cp.async.wait_group 0;" ::: "memory");
        }
        __syncthreads();

        const float* As = smf + (t & 1) * 9216;
        const float* Bs = As + 4608;

        #pragma unroll
        for (int ks = 0; ks < 4; ++ks) {
            const int kk = ks * 8;
            uint32_t bf[4][2];
            #pragma unroll
            for (int nt = 0; nt < 4; ++nt) {
                int col = wn * 32 + nt * 8 + g;
                bf[nt][0] = __float_as_uint(Bs[col * 36 + kk + tig]);
                bf[nt][1] = __float_as_uint(Bs[col * 36 + kk + tig + 4]);
            }
            #pragma unroll
            for (int mt = 0; mt < 4; ++mt) {
                int row = wm * 64 + mt * 16;
                uint32_t a0 = __float_as_uint(As[(row + g    ) * 36 + kk + tig]);
                uint32_t a1 = __float_as_uint(As[(row + g + 8) * 36 + kk + tig]);
                uint32_t a2 = __float_as_uint(As[(row + g    ) * 36 + kk + tig + 4]);
                uint32_t a3 = __float_as_uint(As[(row + g + 8) * 36 + kk + tig + 4]);
                #pragma unroll
                for (int nt = 0; nt < 4; ++nt)
                    mma_tf32(acc[mt][nt], a0, a1, a2, a3, bf[nt][0], bf[nt][1]);
            }
        }
        __syncthreads();
    }

    // ------------------------- epilogue -------------------------
    if (!EXPOUT) {
        #pragma unroll
        for (int mt = 0; mt < 4; ++mt) {
            #pragma unroll
            for (int half = 0; half < 2; ++half) {
                int gm = m0 + wm * 64 + mt * 16 + g + half * 8;
                if (gm >= M) continue;
                float rp = (EPI == 1) ? p1[gm] : 0.f;
                float* crow = C + (size_t)gm * ldc;
                #pragma unroll
                for (int nt = 0; nt < 4; ++nt) {
                    #pragma unroll
                    for (int cc = 0; cc < 2; ++cc) {
                        int gn = n0 + wn * 32 + nt * 8 + tig * 2 + cc;
                        if (gn < Nn) {
                            float v = acc[mt][nt][half * 2 + cc];
                            if (EPI == 0)      v *= alpha;
                            else if (EPI == 1) v += rp;
                            else               v = fmaxf(fmaf(v + p1[gn], p2[gn] * BN_INV, p3[gn]), 0.f);
                            if (ROUND) v = rtf(v);
                            crow[gn] = v;
                        }
                    }
                }
            }
        }
    } else {
        // stage raw scaled scores, then write exp for both orientations
        float* stg = smf;   // 128x129 staging (66 KB); mainloop buffers dead
        #pragma unroll
        for (int mt = 0; mt < 4; ++mt)
            #pragma unroll
            for (int half = 0; half < 2; ++half) {
                int lm = wm * 64 + mt * 16 + g + half * 8;
                #pragma unroll
                for (int nt = 0; nt < 4; ++nt)
                    #pragma unroll
                    for (int cc = 0; cc < 2; ++cc) {
                        int ln = wn * 32 + nt * 8 + tig * 2 + cc;
                        stg[lm * 129 + ln] = acc[mt][nt][half * 2 + cc] * alpha;
                    }
            }
        __syncthreads();
        const int cL = tid & 127, rO = tid >> 7;
        #pragma unroll 4
        for (int j = 0; j < 64; ++j) {
            int r = (j << 1) + rO;
            int gm = m0 + r, gn = n0 + cL;
            if (gm < M && gn < Nn)
                C[(size_t)gm * ldc + gn] = rtf(fexp(stg[r * 129 + cL] - mhat[gm]));
        }
        if (blockIdx.x != blockIdx.y) {
            #pragma unroll 4
            for (int j = 0; j < 64; ++j) {
                int r = (j << 1) + rO;
                int gn = n0 + r, gm = m0 + cL;
                if (gn < Nn && gm < M)
                    C[(size_t)gn * ldc + gm] = rtf(fexp(stg[cL * 129 + r] - mhat[gn]));
            }
        }
    }
}

// ------------------------- y-GEMM: 128x256 tile, 256 thr, warp 64x64 --------
// yT[n,c] = sum_m E[n,m] g[c,m]; each CTA also sums 64 of its E rows -> denom
// 3-stage cp.async pipeline, single __syncthreads per k-tile
#define Y_SMEM 165888   /* 3 stages x (A 18432 + B 36864) */

__global__ void __launch_bounds__(256, 1)
gemm_y(const float* __restrict__ A, const float* __restrict__ B,
       float* __restrict__ C, float* __restrict__ denom) {
    extern __shared__ char dsm[];
    float* smf = (float*)dsm;
    const uint32_t sbase = (uint32_t)__cvta_generic_to_shared(dsm);

    const int tid  = threadIdx.x;
    const int lane = tid & 31, wid = tid >> 5;
    const int wm = wid & 1;          // 2 warp rows (64 m each)
    const int wn = wid >> 1;         // 4 warp cols (64 n each)
    const int g   = lane >> 2;
    const int tig = lane & 3;
    const int m0 = blockIdx.y * 128, n0 = blockIdx.x * 256;
    const int M = NPIX, K = LDF;

    float acc[4][8][4];
    #pragma unroll
    for (int mt = 0; mt < 4; ++mt)
        #pragma unroll
        for (int nt = 0; nt < 8; ++nt)
            #pragma unroll
            for (int c = 0; c < 4; ++c) acc[mt][nt][c] = 0.f;
    float dpart = 0.f;
    // denom rows: this CTA sums A rows [bx*64, bx*64+64); 4 threads per row
    const int drow = (blockIdx.x << 6) + (tid >> 2);   // local row in A tile
    const int dq   = (tid & 3) * 8;                    // 8 floats per thread

    auto issue = [&](int t) {
        const int stage = t % 3;
        uint32_t sa = sbase + (uint32_t)stage * 55296u;
        uint32_t sb = sa + 18432u;
        const int kbase = t << 5;
        #pragma unroll
        for (int i = 0; i < 4; ++i) {        // A: 128 rows x 8 chunks
            int id = tid + (i << 8);
            int row = id >> 3, ch = id & 7;
            int gk = kbase + (ch << 2);
            uint32_t off = (uint32_t)(row * 144 + (ch << 4));
            const float* pa = A + (size_t)(m0 + row) * K + gk;
            int sza = ((m0 + row) < M && gk < K) ? 16 : 0;
            if (!sza) pa = A;
            asm volatile("cp.async.cg.shared.global [%0], [%1], 16, %2;"
                         :: "r"(sa + off), "l"(pa), "r"(sza) : "memory");
        }
        #pragma unroll
        for (int i = 0; i < 8; ++i) {        // B: 256 rows x 8 chunks
            int id = tid + (i << 8);
            int row = id >> 3, ch = id & 7;
            int gk = kbase + (ch << 2);
            uint32_t off = (uint32_t)(row * 144 + (ch << 4));
            const float* pb = B + (size_t)(n0 + row) * K + gk;
            int szb = (gk < K) ? 16 : 0;
            if (!szb) pb = B;
            asm volatile("cp.async.cg.shared.global [%0], [%1], 16, %2;"
                         :: "r"(sb + off), "l"(pb), "r"(szb) : "memory");
        }
        asm volatile("cp.async.commit_group;" ::: "memory");
    };

    const int KT = (K + 31) >> 5;   // 295
    issue(0);
    if (KT > 1) issue(1);
    for (int t = 0; t < KT; ++t) {
        if (t + 1 < KT) asm volatile("cp.async.wait_group 1;" ::: "memory");
        else            asm volatile("cp.async.wait_group 0;" ::: "memory");
        __syncthreads();
        if (t + 2 < KT) issue(t + 2);

        const float* As = smf + (t % 3) * 13824;
        const float* Bs = As + 4608;

        // denom partial: 8 floats of one A row
        {
            float4 v0 = *(const float4*)&As[drow * 36 + dq];
            float4 v1 = *(const float4*)&As[drow * 36 + dq + 4];
            dpart += (v0.x + v0.y) + (v0.z + v0.w) + (v1.x + v1.y) + (v1.z + v1.w);
        }

        #pragma unroll
        for (int ks = 0; ks < 4; ++ks) {
            const int kk = ks * 8;
            uint32_t bf[8][2];
            #pragma unroll
            for (int nt = 0; nt < 8; ++nt) {
                int col = wn * 64 + nt * 8 + g;
                bf[nt][0] = __float_as_uint(Bs[col * 36 + kk + tig]);
                bf[nt][1] = __float_as_uint(Bs[col * 36 + kk + tig + 4]);
            }
            #pragma unroll
            for (int mt = 0; mt < 4; ++mt) {
                int row = wm * 64 + mt * 16;
                uint32_t a0 = __float_as_uint(As[(row + g    ) * 36 + kk + tig]);
                uint32_t a1 = __float_as_uint(As[(row + g + 8) * 36 + kk + tig]);
                uint32_t a2 = __float_as_uint(As[(row + g    ) * 36 + kk + tig + 4]);
                uint32_t a3 = __float_as_uint(As[(row + g + 8) * 36 + kk + tig + 4]);
                #pragma unroll
                for (int nt = 0; nt < 8; ++nt)
                    mma_tf32(acc[mt][nt], a0, a1, a2, a3, bf[nt][0], bf[nt][1]);
            }
        }
    }

    // denom reduce: 4 consecutive lanes share a row
    dpart += __shfl_xor_sync(0xFFFFFFFFu, dpart, 1);
    dpart += __shfl_xor_sync(0xFFFFFFFFu, dpart, 2);
    if ((tid & 3) == 0) {
        int gm = m0 + drow;
        if (gm < M) atomicAdd(&denom[gm], dpart);
    }

    #pragma unroll
    for (int mt = 0; mt < 4; ++mt) {
        #pragma unroll
        for (int half = 0; half < 2; ++half) {
            int gm = m0 + wm * 64 + mt * 16 + g + half * 8;
            if (gm >= M) continue;
            float* crow = C + (size_t)gm * C2N;
            #pragma unroll
            for (int nt = 0; nt < 8; ++nt) {
                #pragma unroll
                for (int cc = 0; cc < 2; ++cc) {
                    int gn = n0 + wn * 64 + nt * 8 + tig * 2 + cc;
                    crow[gn] = acc[mt][nt][half * 2 + cc];
                }
            }
        }
    }
}

// ---------------------------------------------------------------------------
extern "C" void kernel_launch(void* const* d_in, const int* in_sizes, int n_in,
                              void* d_out, int out_size) {
    const float* x       = (const float*)d_in[0];
    const float* pos     = (const float*)d_in[1];
    const float* w_theta = (const float*)d_in[2];
    const float* b_theta = (const float*)d_in[3];
    const float* gamma_t = (const float*)d_in[4];
    const float* beta_t  = (const float*)d_in[5];
    const float* w_g     = (const float*)d_in[6];
    const float* b_g     = (const float*)d_in[7];
    const float* w_out   = (const float*)d_in[8];
    const float* b_out   = (const float*)d_in[9];
    float* out = (float*)d_out;

    cudaFuncSetAttribute(gemm_mma<2,1,0>, cudaFuncAttributeMaxDynamicSharedMemorySize, GEMM_SMEM);
    cudaFuncSetAttribute(gemm_mma<1,1,0>, cudaFuncAttributeMaxDynamicSharedMemorySize, GEMM_SMEM);
    cudaFuncSetAttribute(gemm_mma<0,0,1>, cudaFuncAttributeMaxDynamicSharedMemorySize, GEMM_SMEM);
    cudaFuncSetAttribute(gemm_mma<1,0,0>, cudaFuncAttributeMaxDynamicSharedMemorySize, GEMM_SMEM);
    cudaFuncSetAttribute(gemm_y,          cudaFuncAttributeMaxDynamicSharedMemorySize, Y_SMEM);

    float *p_xmixT, *p_tT, *p_g, *p_f, *p_yT, *p_mhat, *p_denom, *p_wtR, *p_wgR, *p_woR;
    cudaGetSymbolAddress((void**)&p_xmixT, d_xmixT);
    cudaGetSymbolAddress((void**)&p_tT,    d_tT);
    cudaGetSymbolAddress((void**)&p_g,     d_g);
    cudaGetSymbolAddress((void**)&p_f,     d_f);
    cudaGetSymbolAddress((void**)&p_yT,    d_yT);
    cudaGetSymbolAddress((void**)&p_mhat,  d_mhat);
    cudaGetSymbolAddress((void**)&p_denom, d_denom);
    cudaGetSymbolAddress((void**)&p_wtR,   d_wtR);
    cudaGetSymbolAddress((void**)&p_wgR,   d_wgR);
    cudaGetSymbolAddress((void**)&p_woR,   d_woR);

    const int TM = 74;  // ceil(9409/128)

    // 0) reset accumulators (graph-replay safe) + round weights to tf32
    zero_k<<<37, 256>>>();
    round_k<<<(C1N * CMIX + 255) / 256, 256>>>(w_theta, p_wtR, C1N * CMIX);
    round_k<<<(C2N * CMIX + 255) / 256, 256>>>(w_g,     p_wgR, C2N * CMIX);
    round_k<<<(CIN * C2N  + 255) / 256, 256>>>(w_out,   p_woR, CIN * C2N);

    // 1) xmixT = round(concat(x,pos)^T)   [9409, 1024]
    concatT_k<<<dim3(295, 16, 2), dim3(32, 8)>>>(x, pos);

    // 2) tT = round(relu(bn(xmixT @ w_theta^T)))   [9409, 256]
    gemm_mma<2,1,0><<<dim3(2, TM), 256, GEMM_SMEM>>>(
        p_xmixT, p_wtR, p_tT, NPIX, C1N, CMIX, CMIX, CMIX, C1N,
        b_theta, gamma_t, beta_t, 1.f, nullptr);

    // 3) ds[n] = |t_n|^2/16, dsmax; mhat[n] = sqrt(ds[n]*dsmax)  (>= row max)
    ds_k<<<(NPIX + 7) / 8, 256>>>();
    mhat_k<<<37, 256>>>();

    // 4) g = round(w_g @ xmixT^T + b_g)   [512, LDF]
    gemm_mma<1,1,0><<<dim3(TM, 4), 256, GEMM_SMEM>>>(
        p_wgR, p_xmixT, p_g, C2N, NPIX, CMIX, CMIX, CMIX, LDF,
        b_g, nullptr, nullptr, 1.f, nullptr);

    // 5) E = exp(tT@tT^T/16 - mhat[row])  — symmetric tiles + mirror, exp fused
    gemm_mma<0,0,1><<<dim3(TM, TM), 256, GEMM_SMEM>>>(
        p_tT, p_tT, p_f, NPIX, NPIX, C1N, C1N, C1N, LDF,
        nullptr, nullptr, nullptr, 0.0625f, p_mhat);

    // 6) yT[n,c] = sum_m E[n,m] g[c,m]; CTAs also accumulate denom[n]
    gemm_y<<<dim3(2, TM), 256, Y_SMEM>>>(p_f, p_g, p_yT, p_denom);

    // 7) yT *= 1/denom  (tf32-rounded)
    scale_yT_k<<<(NPIX * 128 + 255) / 256, 256>>>();

    // 8) out = w_out @ yT^T + b_out       [512, 9409]
    gemm_mma<1,0,0><<<dim3(TM, 4), 256, GEMM_SMEM>>>(
        p_woR, p_yT, out, CIN, NPIX, C2N, C2N, C2N, NPIX,
        b_out, nullptr, nullptr, 1.f, nullptr);
}

// round 13
// speedup vs baseline: 1.2450x; 1.2419x over previous
#include <cuda_runtime.h>
#include <cuda_fp16.h>
#include <cstdint>
#include <math.h>

#define NPIX 9409
#define LDH  9416          /* half-row stride (mult of 8 halves = 16B) */
#define CIN  512
#define CMIX 1024
#define C1N  256
#define C2N  512
#define BN_INV 0.9999950000374997f

// ------------------------- scratch (static device) --------------------------
__device__ float  d_xmixT[NPIX * CMIX];       // [9409, 1024] (tf32-rounded)
__device__ float  d_tT  [NPIX * C1N];         // [9409, 256]  (tf32-rounded)
__device__ __half d_gh  [C2N * LDH];          // [512, 9416]  fp16 g; pads 0
__device__ __half d_E   [NPIX * LDH];         // [9409, 9416] fp16 E'; pads 0
__device__ float  d_yT  [NPIX * C2N];         // [9409, 512]  rtf(raw)
__device__ float  d_ds  [NPIX];
__device__ float  d_mhat[NPIX];               // sqrt(ds*dsmax) - 7
__device__ float  d_denom[NPIX];
__device__ float  d_rinv[NPIX];
__device__ float  d_dsmax;
__device__ float  d_wtR [C1N * CMIX];
__device__ float  d_wgR [C2N * CMIX];
__device__ float  d_woR [CIN * C2N];

// ------------------------- helpers ------------------------------------------
__device__ __forceinline__ uint32_t f2tf(float v) {
    uint32_t u;
    asm("cvt.rna.tf32.f32 %0, %1;" : "=r"(u) : "f"(v));
    return u;
}
__device__ __forceinline__ float rtf(float v) { return __uint_as_float(f2tf(v)); }

__device__ __forceinline__ void mma_tf32(float c[4], uint32_t a0, uint32_t a1,
                                         uint32_t a2, uint32_t a3,
                                         uint32_t b0, uint32_t b1) {
    asm volatile(
        "mma.sync.aligned.m16n8k8.row.col.f32.tf32.tf32.f32 "
        "{%0,%1,%2,%3}, {%4,%5,%6,%7}, {%8,%9}, {%0,%1,%2,%3};"
        : "+f"(c[0]), "+f"(c[1]), "+f"(c[2]), "+f"(c[3])
        : "r"(a0), "r"(a1), "r"(a2), "r"(a3), "r"(b0), "r"(b1));
}

__device__ __forceinline__ void mma_f16(float c[4], uint32_t a0, uint32_t a1,
                                        uint32_t a2, uint32_t a3,
                                        uint32_t b0, uint32_t b1) {
    asm volatile(
        "mma.sync.aligned.m16n8k16.row.col.f32.f16.f16.f32 "
        "{%0,%1,%2,%3}, {%4,%5,%6,%7}, {%8,%9}, {%0,%1,%2,%3};"
        : "+f"(c[0]), "+f"(c[1]), "+f"(c[2]), "+f"(c[3])
        : "r"(a0), "r"(a1), "r"(a2), "r"(a3), "r"(b0), "r"(b1));
}

// fast exp on the FMA pipe (no MUFU); clamp guarantees finite result
__device__ __forceinline__ float fexp(float x) {
    x = fmaxf(x, -87.0f);
    float t = x * 1.4426950408889634f;
    float fl = floorf(t);
    float f = t - fl;
    float p = 1.52527338e-5f;
    p = fmaf(p, f, 1.54035304e-4f);
    p = fmaf(p, f, 1.33335581e-3f);
    p = fmaf(p, f, 9.61812911e-3f);
    p = fmaf(p, f, 5.55041087e-2f);
    p = fmaf(p, f, 2.40226507e-1f);
    p = fmaf(p, f, 6.93147181e-1f);
    p = fmaf(p, f, 1.0f);
    int i = (int)fl;
    return p * __int_as_float((i + 127) << 23);
}

__device__ __forceinline__ float hsum8(uint4 q) {
    float2 f0 = __half22float2(*(__half2*)&q.x);
    float2 f1 = __half22float2(*(__half2*)&q.y);
    float2 f2 = __half22float2(*(__half2*)&q.z);
    float2 f3 = __half22float2(*(__half2*)&q.w);
    return ((f0.x + f0.y) + (f1.x + f1.y)) + ((f2.x + f2.y) + (f3.x + f3.y));
}

// ------------------------- small prep kernels -------------------------------
__global__ void zero_k() {
    int i = blockIdx.x * 256 + threadIdx.x;
    if (i < NPIX) d_denom[i] = 0.f;
    if (i == 0) d_dsmax = 0.f;
}

__global__ void round_k(const float* __restrict__ in, float* __restrict__ out, int n) {
    int i = blockIdx.x * 256 + threadIdx.x;
    if (i < n) out[i] = rtf(in[i]);
}

__global__ void concatT_k(const float* __restrict__ x, const float* __restrict__ pos) {
    __shared__ float tile[32][33];
    const float* S = blockIdx.z ? pos : x;
    int c0 = blockIdx.y * 32, n0 = blockIdx.x * 32;
    int tx = threadIdx.x, ty = threadIdx.y;
    #pragma unroll
    for (int i = 0; i < 32; i += 8) {
        int c = c0 + ty + i, n = n0 + tx;
        if (n < NPIX) tile[ty + i][tx] = S[(size_t)c * NPIX + n];
    }
    __syncthreads();
    int kbase = blockIdx.z * 512 + c0;
    #pragma unroll
    for (int i = 0; i < 32; i += 8) {
        int n = n0 + ty + i;
        if (n < NPIX) d_xmixT[(size_t)n * CMIX + kbase + tx] = rtf(tile[tx][ty + i]);
    }
}

__global__ void __launch_bounds__(256) ds_k() {
    int row = blockIdx.x * 8 + (threadIdx.x >> 5);
    if (row >= NPIX) return;
    int lane = threadIdx.x & 31;
    const float* p = d_tT + (size_t)row * C1N;
    float s = 0.f;
    #pragma unroll
    for (int i = 0; i < 2; ++i) {
        float4 v = *(const float4*)(p + lane * 8 + i * 4);
        s += v.x * v.x + v.y * v.y + v.z * v.z + v.w * v.w;
    }
    #pragma unroll
    for (int off = 16; off > 0; off >>= 1) s += __shfl_xor_sync(0xFFFFFFFFu, s, off);
    if (lane == 0) {
        float dsv = s * 0.0625f;
        d_ds[row] = dsv;
        atomicMax((int*)&d_dsmax, __float_as_int(dsv));
    }
}

__global__ void mhat_k() {
    int i = blockIdx.x * 256 + threadIdx.x;
    if (i < NPIX) d_mhat[i] = sqrtf(d_ds[i] * d_dsmax) - 7.0f;
}

__global__ void rinv_k() {
    int i = blockIdx.x * 256 + threadIdx.x;
    if (i < NPIX) d_rinv[i] = 1.f / d_denom[i];
}

// ------------------------- mma.sync tf32 GEMM (256 thr), cp.async -----------
// D[M,N] = epi( sum_k A[m,k]*B[n,k] );  A [M,K] lda, B [N,K] ldb, C [M,N] ldc
// EPI 0: *alpha  1: +p1[gm]  2: relu((acc+p1[gn])*p2[gn]*BN_INV+p3[gn])
// EPI 4: acc*p2[gn] + p1[gm]
// HOUT: write __half to ((half*)C)
// EXPOUT: symmetric Gram tiles; writes fp16 E'=exp(v*alpha - mhat[row]) both
//         orientations into half C with LDH stride (only bx>=by launched)
#define GEMM_SMEM 73728

template <int EPI, int ROUND, int EXPOUT, int HOUT>
__global__ void __launch_bounds__(256, 2)
gemm_mma(const float* __restrict__ A, const float* __restrict__ B, float* __restrict__ C,
         int M, int Nn, int K, int lda, int ldb, int ldc,
         const float* __restrict__ p1, const float* __restrict__ p2,
         const float* __restrict__ p3, float alpha,
         const float* __restrict__ mhat) {
    if (EXPOUT && blockIdx.y > blockIdx.x) return;
    extern __shared__ char dsm[];
    float* smf = (float*)dsm;
    const uint32_t sbase = (uint32_t)__cvta_generic_to_shared(dsm);

    const int tid  = threadIdx.x;
    const int lane = tid & 31, wid = tid >> 5;
    const int wm = wid & 1;
    const int wn = wid >> 1;
    const int g   = lane >> 2;
    const int tig = lane & 3;
    const int m0 = blockIdx.y * 128, n0 = blockIdx.x * 128;

    const int lr  = tid >> 3;
    const int kv4 = (tid & 7) << 2;

    float acc[4][4][4];
    #pragma unroll
    for (int mt = 0; mt < 4; ++mt)
        #pragma unroll
        for (int nt = 0; nt < 4; ++nt)
            #pragma unroll
            for (int c = 0; c < 4; ++c) acc[mt][nt][c] = 0.f;

    const int KT = (K + 31) >> 5;

    auto issue = [&](int t) {
        const int gk = (t << 5) + kv4;
        uint32_t sa = sbase + (uint32_t)(t & 1) * 36864u;
        uint32_t sb = sa + 18432u;
        #pragma unroll
        for (int i = 0; i < 4; ++i) {
            int row = lr + (i << 5);
            uint32_t off = (uint32_t)(row * 144 + (kv4 << 2));
            const float* pa = A + (size_t)(m0 + row) * lda + gk;
            int sza = ((m0 + row) < M && gk < K) ? 16 : 0;
            if (!sza) pa = A;
            asm volatile("cp.async.cg.shared.global [%0], [%1], 16, %2;"
                         :: "r"(sa + off), "l"(pa), "r"(sza) : "memory");
            const float* pb = B + (size_t)(n0 + row) * ldb + gk;
            int szb = ((n0 + row) < Nn && gk < K) ? 16 : 0;
            if (!szb) pb = B;
            asm volatile("cp.async.cg.shared.global [%0], [%1], 16, %2;"
                         :: "r"(sb + off), "l"(pb), "r"(szb) : "memory");
        }
        asm volatile("cp.async.commit_group;" ::: "memory");
    };

    issue(0);
    for (int t = 0; t < KT; ++t) {
        if (t + 1 < KT) {
            issue(t + 1);
            asm volatile("cp.async.wait_group 1;" ::: "memory");
        } else {
            asm volatile("cp.async.wait_group 0;" ::: "memory");
        }
        __syncthreads();

        const float* As = smf + (t & 1) * 9216;
        const float* Bs = As + 4608;

        #pragma unroll
        for (int ks = 0; ks < 4; ++ks) {
            const int kk = ks * 8;
            uint32_t bf[4][2];
            #pragma unroll
            for (int nt = 0; nt < 4; ++nt) {
                int col = wn * 32 + nt * 8 + g;
                bf[nt][0] = __float_as_uint(Bs[col * 36 + kk + tig]);
                bf[nt][1] = __float_as_uint(Bs[col * 36 + kk + tig + 4]);
            }
            #pragma unroll
            for (int mt = 0; mt < 4; ++mt) {
                int row = wm * 64 + mt * 16;
                uint32_t a0 = __float_as_uint(As[(row + g    ) * 36 + kk + tig]);
                uint32_t a1 = __float_as_uint(As[(row + g + 8) * 36 + kk + tig]);
                uint32_t a2 = __float_as_uint(As[(row + g    ) * 36 + kk + tig + 4]);
                uint32_t a3 = __float_as_uint(As[(row + g + 8) * 36 + kk + tig + 4]);
                #pragma unroll
                for (int nt = 0; nt < 4; ++nt)
                    mma_tf32(acc[mt][nt], a0, a1, a2, a3, bf[nt][0], bf[nt][1]);
            }
        }
        __syncthreads();
    }

    // ------------------------- epilogue -------------------------
    if (!EXPOUT) {
        #pragma unroll
        for (int mt = 0; mt < 4; ++mt) {
            #pragma unroll
            for (int half_ = 0; half_ < 2; ++half_) {
                int gm = m0 + wm * 64 + mt * 16 + g + half_ * 8;
                if (gm >= M) continue;
                float rp = (EPI == 1 || EPI == 4) ? p1[gm] : 0.f;
                #pragma unroll
                for (int nt = 0; nt < 4; ++nt) {
                    #pragma unroll
                    for (int cc = 0; cc < 2; ++cc) {
                        int gn = n0 + wn * 32 + nt * 8 + tig * 2 + cc;
                        if (gn < Nn) {
                            float v = acc[mt][nt][half_ * 2 + cc];
                            if (EPI == 0)      v *= alpha;
                            else if (EPI == 1) v += rp;
                            else if (EPI == 2) v = fmaxf(fmaf(v + p1[gn], p2[gn] * BN_INV, p3[gn]), 0.f);
                            else               v = fmaf(v, p2[gn], rp);
                            if (ROUND) v = rtf(v);
                            if (HOUT) ((__half*)C)[(size_t)gm * ldc + gn] = __float2half_rn(v);
                            else      C[(size_t)gm * ldc + gn] = v;
                        }
                    }
                }
            }
        }
    } else {
        float* stg = smf;   // 128x129 staging; mainloop buffers dead
        #pragma unroll
        for (int mt = 0; mt < 4; ++mt)
            #pragma unroll
            for (int half_ = 0; half_ < 2; ++half_) {
                int lm = wm * 64 + mt * 16 + g + half_ * 8;
                #pragma unroll
                for (int nt = 0; nt < 4; ++nt)
                    #pragma unroll
                    for (int cc = 0; cc < 2; ++cc) {
                        int ln = wn * 32 + nt * 8 + tig * 2 + cc;
                        stg[lm * 129 + ln] = acc[mt][nt][half_ * 2 + cc] * alpha;
                    }
            }
        __syncthreads();
        __half* Ch = (__half*)C;
        const int cL = tid & 127, rO = tid >> 7;
        #pragma unroll 4
        for (int j = 0; j < 64; ++j) {
            int r = (j << 1) + rO;
            int gm = m0 + r, gn = n0 + cL;
            if (gm < M && gn < Nn)
                Ch[(size_t)gm * LDH + gn] = __float2half_rn(fexp(stg[r * 129 + cL] - mhat[gm]));
        }
        if (blockIdx.x != blockIdx.y) {
            #pragma unroll 4
            for (int j = 0; j < 64; ++j) {
                int r = (j << 1) + rO;
                int gn = n0 + r, gm = m0 + cL;
                if (gn < Nn && gm < M)
                    Ch[(size_t)gn * LDH + gm] = __float2half_rn(fexp(stg[cL * 129 + r] - mhat[gn]));
            }
        }
    }
}

// ------------------------- y-GEMM fp16: 128x256 tile, 256 thr ---------------
// yT[n,c] = sum_m E'[n,m] g[c,m] (fp16 x fp16 -> fp32); bx==0 sums denom
#define Y_SMEM 129024   /* 3 stages x (A 128*112 + B 256*112) */

__global__ void __launch_bounds__(256, 1)
gemm_y16(const __half* __restrict__ A, const __half* __restrict__ B,
         float* __restrict__ C, float* __restrict__ denom) {
    extern __shared__ char dsm[];
    uint32_t* smu = (uint32_t*)dsm;
    const uint32_t sbase = (uint32_t)__cvta_generic_to_shared(dsm);

    const int tid  = threadIdx.x;
    const int lane = tid & 31, wid = tid >> 5;
    const int wm = wid & 1;          // 2 warp rows (64 m each)
    const int wn = wid >> 1;         // 4 warp cols (64 n each)
    const int g   = lane >> 2;
    const int tig = lane & 3;
    const int m0 = blockIdx.y * 128, n0 = blockIdx.x * 256;
    const int M = NPIX, KH = LDH;

    float acc[4][8][4];
    #pragma unroll
    for (int mt = 0; mt < 4; ++mt)
        #pragma unroll
        for (int nt = 0; nt < 8; ++nt)
            #pragma unroll
            for (int c = 0; c < 4; ++c) acc[mt][nt][c] = 0.f;
    float dpart = 0.f;
    const int drow = tid >> 1;          // 0..127
    const int dq   = (tid & 1) * 8;     // uint offset: 8 uints = 16 halves
    const bool dflag = (blockIdx.x == 0);

    auto issue = [&](int t) {
        const int stage = t % 3;
        uint32_t sa = sbase + (uint32_t)stage * 43008u;
        uint32_t sb = sa + 14336u;
        const int kh = t << 5;
        #pragma unroll
        for (int i = 0; i < 2; ++i) {        // A: 128 rows x 4 chunks
            int id = tid + (i << 8);
            int row = id >> 2, ch = id & 3;
            int gk = kh + (ch << 3);
            uint32_t off = (uint32_t)(row * 112 + (ch << 4));
            const __half* pa = A + (size_t)(m0 + row) * LDH + gk;
            int sz = ((m0 + row) < M && gk < KH) ? 16 : 0;
            if (!sz) pa = A;
            asm volatile("cp.async.cg.shared.global [%0], [%1], 16, %2;"
                         :: "r"(sa + off), "l"(pa), "r"(sz) : "memory");
        }
        #pragma unroll
        for (int i = 0; i < 4; ++i) {        // B: 256 rows x 4 chunks
            int id = tid + (i << 8);
            int row = id >> 2, ch = id & 3;
            int gk = kh + (ch << 3);
            uint32_t off = (uint32_t)(row * 112 + (ch << 4));
            const __half* pb = B + (size_t)(n0 + row) * LDH + gk;
            int sz = (gk < KH) ? 16 : 0;
            if (!sz) pb = B;
            asm volatile("cp.async.cg.shared.global [%0], [%1], 16, %2;"
                         :: "r"(sb + off), "l"(pb), "r"(sz) : "memory");
        }
        asm volatile("cp.async.commit_group;" ::: "memory");
    };

    const int KT = (KH + 31) >> 5;   // 295
    issue(0);
    if (KT > 1) issue(1);
    for (int t = 0; t < KT; ++t) {
        if (t + 1 < KT) asm volatile("cp.async.wait_group 1;" ::: "memory");
        else            asm volatile("cp.async.wait_group 0;" ::: "memory");
        __syncthreads();
        if (t + 2 < KT) issue(t + 2);

        const uint32_t* As = smu + (t % 3) * 10752;
        const uint32_t* Bs = As + 3584;

        if (dflag) {   // fp32 row-sum of this k-slab of E'
            uint4 q0 = *(const uint4*)&As[drow * 28 + dq];
            uint4 q1 = *(const uint4*)&As[drow * 28 + dq + 4];
            dpart += hsum8(q0) + hsum8(q1);
        }

        #pragma unroll
        for (int ks = 0; ks < 2; ++ks) {
            const int ko = ks * 8;
            uint32_t bf[8][2];
            #pragma unroll
            for (int nt = 0; nt < 8; ++nt) {
                int col = wn * 64 + nt * 8 + g;
                bf[nt][0] = Bs[col * 28 + ko + tig];
                bf[nt][1] = Bs[col * 28 + ko + tig + 4];
            }
            #pragma unroll
            for (int mt = 0; mt < 4; ++mt) {
                int row = wm * 64 + mt * 16;
                uint32_t a0 = As[(row + g    ) * 28 + ko + tig];
                uint32_t a1 = As[(row + g + 8) * 28 + ko + tig];
                uint32_t a2 = As[(row + g    ) * 28 + ko + tig + 4];
                uint32_t a3 = As[(row + g + 8) * 28 + ko + tig + 4];
                #pragma unroll
                for (int nt = 0; nt < 8; ++nt)
                    mma_f16(acc[mt][nt], a0, a1, a2, a3, bf[nt][0], bf[nt][1]);
            }
        }
    }

    if (dflag) {
        dpart += __shfl_xor_sync(0xFFFFFFFFu, dpart, 1);
        if ((tid & 1) == 0) {
            int gm = m0 + drow;
            if (gm < M) atomicAdd(&denom[gm], dpart);
        }
    }

    #pragma unroll
    for (int mt = 0; mt < 4; ++mt) {
        #pragma unroll
        for (int half_ = 0; half_ < 2; ++half_) {
            int gm = m0 + wm * 64 + mt * 16 + g + half_ * 8;
            if (gm >= M) continue;
            float* crow = C + (size_t)gm * C2N;
            #pragma unroll
            for (int nt = 0; nt < 8; ++nt) {
                #pragma unroll
                for (int cc = 0; cc < 2; ++cc) {
                    int gn = n0 + wn * 64 + nt * 8 + tig * 2 + cc;
                    crow[gn] = rtf(acc[mt][nt][half_ * 2 + cc]);
                }
            }
        }
    }
}

// ---------------------------------------------------------------------------
extern "C" void kernel_launch(void* const* d_in, const int* in_sizes, int n_in,
                              void* d_out, int out_size) {
    const float* x       = (const float*)d_in[0];
    const float* pos     = (const float*)d_in[1];
    const float* w_theta = (const float*)d_in[2];
    const float* b_theta = (const float*)d_in[3];
    const float* gamma_t = (const float*)d_in[4];
    const float* beta_t  = (const float*)d_in[5];
    const float* w_g     = (const float*)d_in[6];
    const float* b_g     = (const float*)d_in[7];
    const float* w_out   = (const float*)d_in[8];
    const float* b_out   = (const float*)d_in[9];
    float* out = (float*)d_out;

    cudaFuncSetAttribute(gemm_mma<2,1,0,0>, cudaFuncAttributeMaxDynamicSharedMemorySize, GEMM_SMEM);
    cudaFuncSetAttribute(gemm_mma<1,0,0,1>, cudaFuncAttributeMaxDynamicSharedMemorySize, GEMM_SMEM);
    cudaFuncSetAttribute(gemm_mma<0,0,1,0>, cudaFuncAttributeMaxDynamicSharedMemorySize, GEMM_SMEM);
    cudaFuncSetAttribute(gemm_mma<4,0,0,0>, cudaFuncAttributeMaxDynamicSharedMemorySize, GEMM_SMEM);
    cudaFuncSetAttribute(gemm_y16,          cudaFuncAttributeMaxDynamicSharedMemorySize, Y_SMEM);

    float *p_xmixT, *p_tT, *p_yT, *p_mhat, *p_denom, *p_rinv, *p_wtR, *p_wgR, *p_woR;
    __half *p_gh, *p_E;
    cudaGetSymbolAddress((void**)&p_xmixT, d_xmixT);
    cudaGetSymbolAddress((void**)&p_tT,    d_tT);
    cudaGetSymbolAddress((void**)&p_gh,    d_gh);
    cudaGetSymbolAddress((void**)&p_E,     d_E);
    cudaGetSymbolAddress((void**)&p_yT,    d_yT);
    cudaGetSymbolAddress((void**)&p_mhat,  d_mhat);
    cudaGetSymbolAddress((void**)&p_denom, d_denom);
    cudaGetSymbolAddress((void**)&p_rinv,  d_rinv);
    cudaGetSymbolAddress((void**)&p_wtR,   d_wtR);
    cudaGetSymbolAddress((void**)&p_wgR,   d_wgR);
    cudaGetSymbolAddress((void**)&p_woR,   d_woR);

    const int TM = 74;  // ceil(9409/128)

    // 0) reset accumulators + round weights to tf32
    zero_k<<<37, 256>>>();
    round_k<<<(C1N * CMIX + 255) / 256, 256>>>(w_theta, p_wtR, C1N * CMIX);
    round_k<<<(C2N * CMIX + 255) / 256, 256>>>(w_g,     p_wgR, C2N * CMIX);
    round_k<<<(CIN * C2N  + 255) / 256, 256>>>(w_out,   p_woR, CIN * C2N);

    // 1) xmixT = round(concat(x,pos)^T)
    concatT_k<<<dim3(295, 16, 2), dim3(32, 8)>>>(x, pos);

    // 2) tT = round(relu(bn(xmixT @ w_theta^T)))
    gemm_mma<2,1,0,0><<<dim3(2, TM), 256, GEMM_SMEM>>>(
        p_xmixT, p_wtR, p_tT, NPIX, C1N, CMIX, CMIX, CMIX, C1N,
        b_theta, gamma_t, beta_t, 1.f, nullptr);

    // 3) ds, dsmax; mhat = sqrt(ds*dsmax) - 7  (CS bound, fp16-range shifted)
    ds_k<<<(NPIX + 7) / 8, 256>>>();
    mhat_k<<<37, 256>>>();

    // 4) g(fp16) = w_g @ xmixT^T + b_g   [512, LDH]
    gemm_mma<1,0,0,1><<<dim3(TM, 4), 256, GEMM_SMEM>>>(
        p_wgR, p_xmixT, (float*)p_gh, C2N, NPIX, CMIX, CMIX, CMIX, LDH,
        b_g, nullptr, nullptr, 1.f, nullptr);

    // 5) E'(fp16) = exp(tT@tT^T/16 - mhat[row]) — symmetric tiles + mirror
    gemm_mma<0,0,1,0><<<dim3(TM, TM), 256, GEMM_SMEM>>>(
        p_tT, p_tT, (float*)p_E, NPIX, NPIX, C1N, C1N, C1N, LDH,
        nullptr, nullptr, nullptr, 0.0625f, p_mhat);

    // 6) yT = rtf(E' @ g^T); bx==0 accumulates denom (fp32)
    gemm_y16<<<dim3(2, TM), 256, Y_SMEM>>>(p_E, p_gh, p_yT, p_denom);

    // 7) rinv = 1/denom
    rinv_k<<<37, 256>>>();

    // 8) out = (w_out @ yT^T) * rinv[n] + b_out
    gemm_mma<4,0,0,0><<<dim3(TM, 4), 256, GEMM_SMEM>>>(
        p_woR, p_yT, out, CIN, NPIX, C2N, C2N, C2N, NPIX,
        b_out, p_rinv, nullptr, 1.f, nullptr);
}

// round 14
// speedup vs baseline: 1.3808x; 1.1090x over previous
#include <cuda_runtime.h>
#include <cuda_fp16.h>
#include <cstdint>
#include <math.h>

#define NPIX 9409
#define LDH  9416          /* half-row stride (mult of 8 halves = 16B) */
#define CIN  512
#define CMIX 1024
#define C1N  256
#define C2N  512
#define BN_INV 0.9999950000374997f

// ------------------------- scratch (static device) --------------------------
__device__ float  d_xmixT[NPIX * CMIX];       // [9409, 1024] (tf32-rounded)
__device__ float  d_tT  [NPIX * C1N];         // [9409, 256]  (tf32-rounded)
__device__ __half d_gh  [C2N * LDH];          // [512, 9416]  fp16 g; pads 0
__device__ __half d_E   [NPIX * LDH];         // [9409, 9416] fp16 E'; pads 0
__device__ float  d_yT  [NPIX * C2N];         // [9409, 512]  rtf(raw)
__device__ float  d_ds  [NPIX];
__device__ float  d_mhat[NPIX];               // sqrt(ds*dsmax) - 7
__device__ float  d_denom[NPIX];
__device__ float  d_rinv[NPIX];
__device__ float  d_dsmax;
__device__ float  d_wtR [C1N * CMIX];
__device__ float  d_wgR [C2N * CMIX];
__device__ float  d_woR [CIN * C2N];

// ------------------------- helpers ------------------------------------------
__device__ __forceinline__ uint32_t f2tf(float v) {
    uint32_t u;
    asm("cvt.rna.tf32.f32 %0, %1;" : "=r"(u) : "f"(v));
    return u;
}
__device__ __forceinline__ float rtf(float v) { return __uint_as_float(f2tf(v)); }

__device__ __forceinline__ void mma_tf32(float c[4], uint32_t a0, uint32_t a1,
                                         uint32_t a2, uint32_t a3,
                                         uint32_t b0, uint32_t b1) {
    asm volatile(
        "mma.sync.aligned.m16n8k8.row.col.f32.tf32.tf32.f32 "
        "{%0,%1,%2,%3}, {%4,%5,%6,%7}, {%8,%9}, {%0,%1,%2,%3};"
        : "+f"(c[0]), "+f"(c[1]), "+f"(c[2]), "+f"(c[3])
        : "r"(a0), "r"(a1), "r"(a2), "r"(a3), "r"(b0), "r"(b1));
}

__device__ __forceinline__ void mma_f16(float c[4], uint32_t a0, uint32_t a1,
                                        uint32_t a2, uint32_t a3,
                                        uint32_t b0, uint32_t b1) {
    asm volatile(
        "mma.sync.aligned.m16n8k16.row.col.f32.f16.f16.f32 "
        "{%0,%1,%2,%3}, {%4,%5,%6,%7}, {%8,%9}, {%0,%1,%2,%3};"
        : "+f"(c[0]), "+f"(c[1]), "+f"(c[2]), "+f"(c[3])
        : "r"(a0), "r"(a1), "r"(a2), "r"(a3), "r"(b0), "r"(b1));
}

#define LDMX4(r0, r1, r2, r3, a) \
    asm volatile("ldmatrix.sync.aligned.m8n8.x4.shared.b16 {%0,%1,%2,%3}, [%4];" \
        : "=r"(r0), "=r"(r1), "=r"(r2), "=r"(r3) : "r"(a))

// fast exp on the FMA pipe (no MUFU); clamp guarantees finite result
__device__ __forceinline__ float fexp(float x) {
    x = fmaxf(x, -87.0f);
    float t = x * 1.4426950408889634f;
    float fl = floorf(t);
    float f = t - fl;
    float p = 1.52527338e-5f;
    p = fmaf(p, f, 1.54035304e-4f);
    p = fmaf(p, f, 1.33335581e-3f);
    p = fmaf(p, f, 9.61812911e-3f);
    p = fmaf(p, f, 5.55041087e-2f);
    p = fmaf(p, f, 2.40226507e-1f);
    p = fmaf(p, f, 6.93147181e-1f);
    p = fmaf(p, f, 1.0f);
    int i = (int)fl;
    return p * __int_as_float((i + 127) << 23);
}

__device__ __forceinline__ float hsum8(uint4 q) {
    float2 f0 = __half22float2(*(__half2*)&q.x);
    float2 f1 = __half22float2(*(__half2*)&q.y);
    float2 f2 = __half22float2(*(__half2*)&q.z);
    float2 f3 = __half22float2(*(__half2*)&q.w);
    return ((f0.x + f0.y) + (f1.x + f1.y)) + ((f2.x + f2.y) + (f3.x + f3.y));
}

// ------------------------- small prep kernels -------------------------------
__global__ void zero_k() {
    int i = blockIdx.x * 256 + threadIdx.x;
    if (i < NPIX) d_denom[i] = 0.f;
    if (i == 0) d_dsmax = 0.f;
}

__global__ void round_k(const float* __restrict__ in, float* __restrict__ out, int n) {
    int i = blockIdx.x * 256 + threadIdx.x;
    if (i < n) out[i] = rtf(in[i]);
}

__global__ void concatT_k(const float* __restrict__ x, const float* __restrict__ pos) {
    __shared__ float tile[32][33];
    const float* S = blockIdx.z ? pos : x;
    int c0 = blockIdx.y * 32, n0 = blockIdx.x * 32;
    int tx = threadIdx.x, ty = threadIdx.y;
    #pragma unroll
    for (int i = 0; i < 32; i += 8) {
        int c = c0 + ty + i, n = n0 + tx;
        if (n < NPIX) tile[ty + i][tx] = S[(size_t)c * NPIX + n];
    }
    __syncthreads();
    int kbase = blockIdx.z * 512 + c0;
    #pragma unroll
    for (int i = 0; i < 32; i += 8) {
        int n = n0 + ty + i;
        if (n < NPIX) d_xmixT[(size_t)n * CMIX + kbase + tx] = rtf(tile[tx][ty + i]);
    }
}

__global__ void __launch_bounds__(256) ds_k() {
    int row = blockIdx.x * 8 + (threadIdx.x >> 5);
    if (row >= NPIX) return;
    int lane = threadIdx.x & 31;
    const float* p = d_tT + (size_t)row * C1N;
    float s = 0.f;
    #pragma unroll
    for (int i = 0; i < 2; ++i) {
        float4 v = *(const float4*)(p + lane * 8 + i * 4);
        s += v.x * v.x + v.y * v.y + v.z * v.z + v.w * v.w;
    }
    #pragma unroll
    for (int off = 16; off > 0; off >>= 1) s += __shfl_xor_sync(0xFFFFFFFFu, s, off);
    if (lane == 0) {
        float dsv = s * 0.0625f;
        d_ds[row] = dsv;
        atomicMax((int*)&d_dsmax, __float_as_int(dsv));
    }
}

__global__ void mhat_k() {
    int i = blockIdx.x * 256 + threadIdx.x;
    if (i < NPIX) d_mhat[i] = sqrtf(d_ds[i] * d_dsmax) - 7.0f;
}

__global__ void rinv_k() {
    int i = blockIdx.x * 256 + threadIdx.x;
    if (i < NPIX) d_rinv[i] = 1.f / d_denom[i];
}

// ------------------------- mma.sync tf32 GEMM (256 thr), cp.async -----------
// D[M,N] = epi( sum_k A[m,k]*B[n,k] );  A [M,K] lda, B [N,K] ldb, C [M,N] ldc
// EPI 0: *alpha  1: +p1[gm]  2: relu((acc+p1[gn])*p2[gn]*BN_INV+p3[gn])
// EPI 4: acc*p2[gn] + p1[gm]
// HOUT: write __half to ((half*)C)
// EXPOUT: symmetric Gram tiles; writes fp16 E'=exp(v*alpha - mhat[row]) both
//         orientations into half C with LDH stride (only bx>=by launched)
#define GEMM_SMEM 73728

template <int EPI, int ROUND, int EXPOUT, int HOUT>
__global__ void __launch_bounds__(256, 2)
gemm_mma(const float* __restrict__ A, const float* __restrict__ B, float* __restrict__ C,
         int M, int Nn, int K, int lda, int ldb, int ldc,
         const float* __restrict__ p1, const float* __restrict__ p2,
         const float* __restrict__ p3, float alpha,
         const float* __restrict__ mhat) {
    if (EXPOUT && blockIdx.y > blockIdx.x) return;
    extern __shared__ char dsm[];
    float* smf = (float*)dsm;
    const uint32_t sbase = (uint32_t)__cvta_generic_to_shared(dsm);

    const int tid  = threadIdx.x;
    const int lane = tid & 31, wid = tid >> 5;
    const int wm = wid & 1;
    const int wn = wid >> 1;
    const int g   = lane >> 2;
    const int tig = lane & 3;
    const int m0 = blockIdx.y * 128, n0 = blockIdx.x * 128;

    const int lr  = tid >> 3;
    const int kv4 = (tid & 7) << 2;

    float acc[4][4][4];
    #pragma unroll
    for (int mt = 0; mt < 4; ++mt)
        #pragma unroll
        for (int nt = 0; nt < 4; ++nt)
            #pragma unroll
            for (int c = 0; c < 4; ++c) acc[mt][nt][c] = 0.f;

    const int KT = (K + 31) >> 5;

    auto issue = [&](int t) {
        const int gk = (t << 5) + kv4;
        uint32_t sa = sbase + (uint32_t)(t & 1) * 36864u;
        uint32_t sb = sa + 18432u;
        #pragma unroll
        for (int i = 0; i < 4; ++i) {
            int row = lr + (i << 5);
            uint32_t off = (uint32_t)(row * 144 + (kv4 << 2));
            const float* pa = A + (size_t)(m0 + row) * lda + gk;
            int sza = ((m0 + row) < M && gk < K) ? 16 : 0;
            if (!sza) pa = A;
            asm volatile("cp.async.cg.shared.global [%0], [%1], 16, %2;"
                         :: "r"(sa + off), "l"(pa), "r"(sza) : "memory");
            const float* pb = B + (size_t)(n0 + row) * ldb + gk;
            int szb = ((n0 + row) < Nn && gk < K) ? 16 : 0;
            if (!szb) pb = B;
            asm volatile("cp.async.cg.shared.global [%0], [%1], 16, %2;"
                         :: "r"(sb + off), "l"(pb), "r"(szb) : "memory");
        }
        asm volatile("cp.async.commit_group;" ::: "memory");
    };

    issue(0);
    for (int t = 0; t < KT; ++t) {
        if (t + 1 < KT) {
            issue(t + 1);
            asm volatile("cp.async.wait_group 1;" ::: "memory");
        } else {
            asm volatile("cp.async.wait_group 0;" ::: "memory");
        }
        __syncthreads();

        const float* As = smf + (t & 1) * 9216;
        const float* Bs = As + 4608;

        #pragma unroll
        for (int ks = 0; ks < 4; ++ks) {
            const int kk = ks * 8;
            uint32_t bf[4][2];
            #pragma unroll
            for (int nt = 0; nt < 4; ++nt) {
                int col = wn * 32 + nt * 8 + g;
                bf[nt][0] = __float_as_uint(Bs[col * 36 + kk + tig]);
                bf[nt][1] = __float_as_uint(Bs[col * 36 + kk + tig + 4]);
            }
            #pragma unroll
            for (int mt = 0; mt < 4; ++mt) {
                int row = wm * 64 + mt * 16;
                uint32_t a0 = __float_as_uint(As[(row + g    ) * 36 + kk + tig]);
                uint32_t a1 = __float_as_uint(As[(row + g + 8) * 36 + kk + tig]);
                uint32_t a2 = __float_as_uint(As[(row + g    ) * 36 + kk + tig + 4]);
                uint32_t a3 = __float_as_uint(As[(row + g + 8) * 36 + kk + tig + 4]);
                #pragma unroll
                for (int nt = 0; nt < 4; ++nt)
                    mma_tf32(acc[mt][nt], a0, a1, a2, a3, bf[nt][0], bf[nt][1]);
            }
        }
        __syncthreads();
    }

    // ------------------------- epilogue -------------------------
    if (!EXPOUT) {
        #pragma unroll
        for (int mt = 0; mt < 4; ++mt) {
            #pragma unroll
            for (int half_ = 0; half_ < 2; ++half_) {
                int gm = m0 + wm * 64 + mt * 16 + g + half_ * 8;
                if (gm >= M) continue;
                float rp = (EPI == 1 || EPI == 4) ? p1[gm] : 0.f;
                #pragma unroll
                for (int nt = 0; nt < 4; ++nt) {
                    #pragma unroll
                    for (int cc = 0; cc < 2; ++cc) {
                        int gn = n0 + wn * 32 + nt * 8 + tig * 2 + cc;
                        if (gn < Nn) {
                            float v = acc[mt][nt][half_ * 2 + cc];
                            if (EPI == 0)      v *= alpha;
                            else if (EPI == 1) v += rp;
                            else if (EPI == 2) v = fmaxf(fmaf(v + p1[gn], p2[gn] * BN_INV, p3[gn]), 0.f);
                            else               v = fmaf(v, p2[gn], rp);
                            if (ROUND) v = rtf(v);
                            if (HOUT) ((__half*)C)[(size_t)gm * ldc + gn] = __float2half_rn(v);
                            else      C[(size_t)gm * ldc + gn] = v;
                        }
                    }
                }
            }
        }
    } else {
        float* stg = smf;   // 128x129 staging; mainloop buffers dead
        #pragma unroll
        for (int mt = 0; mt < 4; ++mt)
            #pragma unroll
            for (int half_ = 0; half_ < 2; ++half_) {
                int lm = wm * 64 + mt * 16 + g + half_ * 8;
                #pragma unroll
                for (int nt = 0; nt < 4; ++nt)
                    #pragma unroll
                    for (int cc = 0; cc < 2; ++cc) {
                        int ln = wn * 32 + nt * 8 + tig * 2 + cc;
                        stg[lm * 129 + ln] = acc[mt][nt][half_ * 2 + cc] * alpha;
                    }
            }
        __syncthreads();
        __half* Ch = (__half*)C;
        const int cL = tid & 127, rO = tid >> 7;
        #pragma unroll 4
        for (int j = 0; j < 64; ++j) {
            int r = (j << 1) + rO;
            int gm = m0 + r, gn = n0 + cL;
            if (gm < M && gn < Nn)
                Ch[(size_t)gm * LDH + gn] = __float2half_rn(fexp(stg[r * 129 + cL] - mhat[gm]));
        }
        if (blockIdx.x != blockIdx.y) {
            #pragma unroll 4
            for (int j = 0; j < 64; ++j) {
                int r = (j << 1) + rO;
                int gn = n0 + r, gm = m0 + cL;
                if (gn < Nn && gm < M)
                    Ch[(size_t)gn * LDH + gm] = __float2half_rn(fexp(stg[cL * 129 + r] - mhat[gn]));
            }
        }
    }
}

// ------------------------- y-GEMM fp16: 128x256 tile, k64, ldmatrix ---------
// yT[n,c] = sum_m E'[n,m] g[c,m] (fp16 x fp16 -> fp32); bx==0 sums denom
// SMEM rows padded to 144B (36 banks = 4 mod 32 -> ldmatrix conflict-free)
#define Y_SMEM 165888   /* 3 stages x (A 128*144 + B 256*144) */

__global__ void __launch_bounds__(256, 1)
gemm_y16(const __half* __restrict__ A, const __half* __restrict__ B,
         float* __restrict__ C, float* __restrict__ denom) {
    extern __shared__ char dsm[];
    uint32_t* smu = (uint32_t*)dsm;
    const uint32_t sbase = (uint32_t)__cvta_generic_to_shared(dsm);

    const int tid  = threadIdx.x;
    const int lane = tid & 31, wid = tid >> 5;
    const int wm = wid & 1;          // 2 warp rows (64 m each)
    const int wn = wid >> 1;         // 4 warp cols (64 n each)
    const int g   = lane >> 2;
    const int tig = lane & 3;
    const int m0 = blockIdx.y * 128, n0 = blockIdx.x * 256;
    const int M = NPIX, KH = LDH;

    // ldmatrix per-lane geometry
    const int lrow16 = lane & 15;                 // A: row within 16
    const int lkA    = (lane >> 4) << 4;          // A: kbyte 0/16
    const int lrowB  = (lane & 7) + ((lane >> 4) << 3);  // B: row within 16
    const int lkB    = ((lane >> 3) & 1) << 4;    // B: kbyte 0/16

    float acc[4][8][4];
    #pragma unroll
    for (int mt = 0; mt < 4; ++mt)
        #pragma unroll
        for (int nt = 0; nt < 8; ++nt)
            #pragma unroll
            for (int c = 0; c < 4; ++c) acc[mt][nt][c] = 0.f;
    float dpart = 0.f;
    const int drow = tid >> 1;          // 0..127
    const int dw   = (tid & 1) * 16;    // word offset: 16 words = 32 halves
    const bool dflag = (blockIdx.x == 0);

    auto issue = [&](int t) {
        const int stage = t % 3;
        uint32_t sa = sbase + (uint32_t)stage * 55296u;
        uint32_t sb = sa + 18432u;
        const int kh = t << 6;
        #pragma unroll
        for (int i = 0; i < 4; ++i) {        // A: 128 rows x 8 chunks(16B)
            int id = tid + (i << 8);
            int row = id >> 3, ch = id & 7;
            int gk = kh + (ch << 3);
            uint32_t off = (uint32_t)(row * 144 + (ch << 4));
            const __half* pa = A + (size_t)(m0 + row) * LDH + gk;
            int sz = ((m0 + row) < M && gk < KH) ? 16 : 0;
            if (!sz) pa = A;
            asm volatile("cp.async.cg.shared.global [%0], [%1], 16, %2;"
                         :: "r"(sa + off), "l"(pa), "r"(sz) : "memory");
        }
        #pragma unroll
        for (int i = 0; i < 8; ++i) {        // B: 256 rows x 8 chunks
            int id = tid + (i << 8);
            int row = id >> 3, ch = id & 7;
            int gk = kh + (ch << 3);
            uint32_t off = (uint32_t)(row * 144 + (ch << 4));
            const __half* pb = B + (size_t)(n0 + row) * LDH + gk;
            int sz = (gk < KH) ? 16 : 0;
            if (!sz) pb = B;
            asm volatile("cp.async.cg.shared.global [%0], [%1], 16, %2;"
                         :: "r"(sb + off), "l"(pb), "r"(sz) : "memory");
        }
        asm volatile("cp.async.commit_group;" ::: "memory");
    };

    const int KT = (KH + 63) >> 6;   // 148
    issue(0);
    if (KT > 1) issue(1);
    for (int t = 0; t < KT; ++t) {
        if (t + 1 < KT) asm volatile("cp.async.wait_group 1;" ::: "memory");
        else            asm volatile("cp.async.wait_group 0;" ::: "memory");
        __syncthreads();
        if (t + 2 < KT) issue(t + 2);

        const uint32_t sa = sbase + (uint32_t)(t % 3) * 55296u;
        const uint32_t sb = sa + 18432u;
        const uint32_t* As = smu + (t % 3) * 13824;

        if (dflag) {   // fp32 row-sum of this k-slab of E' (32 words/row)
            const uint32_t* pr = As + drow * 36 + dw;
            uint4 q0 = *(const uint4*)(pr);
            uint4 q1 = *(const uint4*)(pr + 4);
            uint4 q2 = *(const uint4*)(pr + 8);
            uint4 q3 = *(const uint4*)(pr + 12);
            dpart += (hsum8(q0) + hsum8(q1)) + (hsum8(q2) + hsum8(q3));
        }

        const uint32_t aBase = sa + (uint32_t)((wm * 64 + lrow16) * 144 + lkA);
        const uint32_t bBase = sb + (uint32_t)((wn * 64 + lrowB) * 144 + lkB);

        #pragma unroll
        for (int ks = 0; ks < 4; ++ks) {
            const uint32_t ko = (uint32_t)(ks << 5);
            uint32_t bf[8][2];
            #pragma unroll
            for (int pr2 = 0; pr2 < 4; ++pr2)
                LDMX4(bf[2 * pr2][0], bf[2 * pr2][1], bf[2 * pr2 + 1][0], bf[2 * pr2 + 1][1],
                      bBase + (uint32_t)(pr2 * 16 * 144) + ko);
            #pragma unroll
            for (int mt = 0; mt < 4; ++mt) {
                uint32_t a0, a1, a2, a3;
                LDMX4(a0, a1, a2, a3, aBase + (uint32_t)(mt * 16 * 144) + ko);
                #pragma unroll
                for (int nt = 0; nt < 8; ++nt)
                    mma_f16(acc[mt][nt], a0, a1, a2, a3, bf[nt][0], bf[nt][1]);
            }
        }
    }

    if (dflag) {
        dpart += __shfl_xor_sync(0xFFFFFFFFu, dpart, 1);
        if ((tid & 1) == 0) {
            int gm = m0 + drow;
            if (gm < M) atomicAdd(&denom[gm], dpart);
        }
    }

    #pragma unroll
    for (int mt = 0; mt < 4; ++mt) {
        #pragma unroll
        for (int half_ = 0; half_ < 2; ++half_) {
            int gm = m0 + wm * 64 + mt * 16 + g + half_ * 8;
            if (gm >= M) continue;
            float* crow = C + (size_t)gm * C2N;
            #pragma unroll
            for (int nt = 0; nt < 8; ++nt) {
                #pragma unroll
                for (int cc = 0; cc < 2; ++cc) {
                    int gn = n0 + wn * 64 + nt * 8 + tig * 2 + cc;
                    crow[gn] = rtf(acc[mt][nt][half_ * 2 + cc]);
                }
            }
        }
    }
}

// ---------------------------------------------------------------------------
extern "C" void kernel_launch(void* const* d_in, const int* in_sizes, int n_in,
                              void* d_out, int out_size) {
    const float* x       = (const float*)d_in[0];
    const float* pos     = (const float*)d_in[1];
    const float* w_theta = (const float*)d_in[2];
    const float* b_theta = (const float*)d_in[3];
    const float* gamma_t = (const float*)d_in[4];
    const float* beta_t  = (const float*)d_in[5];
    const float* w_g     = (const float*)d_in[6];
    const float* b_g     = (const float*)d_in[7];
    const float* w_out   = (const float*)d_in[8];
    const float* b_out   = (const float*)d_in[9];
    float* out = (float*)d_out;

    cudaFuncSetAttribute(gemm_mma<2,1,0,0>, cudaFuncAttributeMaxDynamicSharedMemorySize, GEMM_SMEM);
    cudaFuncSetAttribute(gemm_mma<1,0,0,1>, cudaFuncAttributeMaxDynamicSharedMemorySize, GEMM_SMEM);
    cudaFuncSetAttribute(gemm_mma<0,0,1,0>, cudaFuncAttributeMaxDynamicSharedMemorySize, GEMM_SMEM);
    cudaFuncSetAttribute(gemm_mma<4,0,0,0>, cudaFuncAttributeMaxDynamicSharedMemorySize, GEMM_SMEM);
    cudaFuncSetAttribute(gemm_y16,          cudaFuncAttributeMaxDynamicSharedMemorySize, Y_SMEM);

    float *p_xmixT, *p_tT, *p_yT, *p_mhat, *p_denom, *p_rinv, *p_wtR, *p_wgR, *p_woR;
    __half *p_gh, *p_E;
    cudaGetSymbolAddress((void**)&p_xmixT, d_xmixT);
    cudaGetSymbolAddress((void**)&p_tT,    d_tT);
    cudaGetSymbolAddress((void**)&p_gh,    d_gh);
    cudaGetSymbolAddress((void**)&p_E,     d_E);
    cudaGetSymbolAddress((void**)&p_yT,    d_yT);
    cudaGetSymbolAddress((void**)&p_mhat,  d_mhat);
    cudaGetSymbolAddress((void**)&p_denom, d_denom);
    cudaGetSymbolAddress((void**)&p_rinv,  d_rinv);
    cudaGetSymbolAddress((void**)&p_wtR,   d_wtR);
    cudaGetSymbolAddress((void**)&p_wgR,   d_wgR);
    cudaGetSymbolAddress((void**)&p_woR,   d_woR);

    const int TM = 74;  // ceil(9409/128)

    // 0) reset accumulators + round weights to tf32
    zero_k<<<37, 256>>>();
    round_k<<<(C1N * CMIX + 255) / 256, 256>>>(w_theta, p_wtR, C1N * CMIX);
    round_k<<<(C2N * CMIX + 255) / 256, 256>>>(w_g,     p_wgR, C2N * CMIX);
    round_k<<<(CIN * C2N  + 255) / 256, 256>>>(w_out,   p_woR, CIN * C2N);

    // 1) xmixT = round(concat(x,pos)^T)
    concatT_k<<<dim3(295, 16, 2), dim3(32, 8)>>>(x, pos);

    // 2) tT = round(relu(bn(xmixT @ w_theta^T)))
    gemm_mma<2,1,0,0><<<dim3(2, TM), 256, GEMM_SMEM>>>(
        p_xmixT, p_wtR, p_tT, NPIX, C1N, CMIX, CMIX, CMIX, C1N,
        b_theta, gamma_t, beta_t, 1.f, nullptr);

    // 3) ds, dsmax; mhat = sqrt(ds*dsmax) - 7  (CS bound, fp16-range shifted)
    ds_k<<<(NPIX + 7) / 8, 256>>>();
    mhat_k<<<37, 256>>>();

    // 4) g(fp16) = w_g @ xmixT^T + b_g   [512, LDH]
    gemm_mma<1,0,0,1><<<dim3(TM, 4), 256, GEMM_SMEM>>>(
        p_wgR, p_xmixT, (float*)p_gh, C2N, NPIX, CMIX, CMIX, CMIX, LDH,
        b_g, nullptr, nullptr, 1.f, nullptr);

    // 5) E'(fp16) = exp(tT@tT^T/16 - mhat[row]) — symmetric tiles + mirror
    gemm_mma<0,0,1,0><<<dim3(TM, TM), 256, GEMM_SMEM>>>(
        p_tT, p_tT, (float*)p_E, NPIX, NPIX, C1N, C1N, C1N, LDH,
        nullptr, nullptr, nullptr, 0.0625f, p_mhat);

    // 6) yT = rtf(E' @ g^T); bx==0 accumulates denom (fp32)
    gemm_y16<<<dim3(2, TM), 256, Y_SMEM>>>(p_E, p_gh, p_yT, p_denom);

    // 7) rinv = 1/denom
    rinv_k<<<37, 256>>>();

    // 8) out = (w_out @ yT^T) * rinv[n] + b_out
    gemm_mma<4,0,0,0><<<dim3(TM, 4), 256, GEMM_SMEM>>>(
        p_woR, p_yT, out, CIN, NPIX, C2N, C2N, C2N, NPIX,
        b_out, p_rinv, nullptr, 1.f, nullptr);
}